// round 9
// baseline (speedup 1.0000x reference)
#include <cuda_runtime.h>
#include <cuda_fp16.h>
#include <math.h>
#include <stdint.h>

#define NN 50000
#define EE 800000
#define BB 256
#define DD 128
#define TT 8
#define KV_OFF (BB*TT*DD)

// ---------------- scratch (no allocations allowed) ----------------
__device__ __half g_h16[(size_t)NN*DD];     // post-attention node states (fp16)
__device__ float  g_KV[2*BB*TT*DD];         // Kc then Vc (fp32)
__device__ float  g_lip[BB*9];              // lattice inner products
__device__ float  g_agg[(size_t)NN*DD];     // scatter sums (fp32 atomics)
__device__ int    g_cnt[NN];                // scatter counts
// pre-converted, pre-transposed fp16 weights [N][K]
__device__ __half g_ew1T[DD*272];
__device__ __half g_ew2T[DD*DD];
__device__ __half g_nw1T[DD*256];
__device__ __half g_nw2T[DD*DD];

__device__ __forceinline__ float silu_f(float x) {
    return __fdividef(x, 1.f + __expf(-x));
}

// tf32 mma (attention kernel only)
__device__ __forceinline__ void mma_tf32(float* c, const uint32_t* a, const uint32_t* b) {
    asm volatile(
        "mma.sync.aligned.m16n8k8.row.col.f32.tf32.tf32.f32 "
        "{%0,%1,%2,%3}, {%4,%5,%6,%7}, {%8,%9}, {%0,%1,%2,%3};\n"
        : "+f"(c[0]), "+f"(c[1]), "+f"(c[2]), "+f"(c[3])
        : "r"(a[0]), "r"(a[1]), "r"(a[2]), "r"(a[3]), "r"(b[0]), "r"(b[1]));
}
// fp16 mma, fp32 accumulate
__device__ __forceinline__ void mma_f16(float* c, const uint32_t* a, const uint32_t* b) {
    asm volatile(
        "mma.sync.aligned.m16n8k16.row.col.f32.f16.f16.f32 "
        "{%0,%1,%2,%3}, {%4,%5,%6,%7}, {%8,%9}, {%0,%1,%2,%3};\n"
        : "+f"(c[0]), "+f"(c[1]), "+f"(c[2]), "+f"(c[3])
        : "r"(a[0]), "r"(a[1]), "r"(a[2]), "r"(a[3]), "r"(b[0]), "r"(b[1]));
}

__device__ __forceinline__ void cpa16(void* dst, const void* src) {
    uint32_t d = (uint32_t)__cvta_generic_to_shared(dst);
    asm volatile("cp.async.cg.shared.global [%0], [%1], 16;" :: "r"(d), "l"(src));
}
#define CP_COMMIT asm volatile("cp.async.commit_group;" ::: "memory")
#define CP_WAIT0  asm volatile("cp.async.wait_group 0;" ::: "memory")

// -------- fp16 fragment loads (A row-major [m][k], B as [n][k]) --------
#define LDA16(afr, base, SAx, rowbase, kg)                                        \
    {                                                                             \
        const __half* ap_ = (base) + ((rowbase) + (lane >> 2))*(SAx) + (kg) + ((lane & 3)*2); \
        afr[0] = *(const uint32_t*)(ap_);                                         \
        afr[1] = *(const uint32_t*)(ap_ + 8*(SAx));                               \
        afr[2] = *(const uint32_t*)(ap_ + 8);                                     \
        afr[3] = *(const uint32_t*)(ap_ + 8*(SAx) + 8);                           \
    }
#define LDB16(bfr, bB, SBx, ncol)                                                 \
    {                                                                             \
        const __half* bp_ = (bB) + ((ncol) + (lane >> 2))*(SBx) + ((lane & 3)*2); \
        bfr[0] = *(const uint32_t*)(bp_);                                         \
        bfr[1] = *(const uint32_t*)(bp_ + 8);                                     \
    }

// tf32 frag loads (attn)
#define SB 136
#define BBF (16*SB)
#define LOAD_AFRAG(afr, s_a, SAx, rowbase, kg)                                   \
    {                                                                            \
        const float* ap_ = (s_a) + ((rowbase) + (lane >> 2))*(SAx) + (kg) + (lane & 3); \
        afr[0] = __float_as_uint(ap_[0]);                                        \
        afr[1] = __float_as_uint(ap_[8*(SAx)]);                                  \
        afr[2] = __float_as_uint(ap_[4]);                                        \
        afr[3] = __float_as_uint(ap_[8*(SAx) + 4]);                              \
    }
#define LOAD_BFRAG(bfr, bB, kk, ncol)                                            \
    {                                                                            \
        const float* bp_ = (bB) + ((kk) + (lane & 3))*SB + (ncol) + (lane >> 2); \
        bfr[0] = __float_as_uint(bp_[0]);                                        \
        bfr[1] = __float_as_uint(bp_[4*SB]);                                     \
    }

// ---------------- kernel 1: K/V projection + lattice gram ----------------
__global__ void prep_kernel(const float* __restrict__ cond,
                            const float* __restrict__ wk, const float* __restrict__ bk,
                            const float* __restrict__ wv, const float* __restrict__ bv,
                            const float* __restrict__ lat)
{
    int b = blockIdx.x;
    if (b < BB*TT) {
        __shared__ float s_c[DD];
        int d = threadIdx.x;
        s_c[d] = cond[b*DD + d];
        __syncthreads();
        float ka = bk[d], va = bv[d];
        #pragma unroll 8
        for (int k = 0; k < DD; k++) {
            float c = s_c[k];
            ka = fmaf(c, wk[k*DD + d], ka);
            va = fmaf(c, wv[k*DD + d], va);
        }
        g_KV[b*DD + d] = ka;
        g_KV[KV_OFF + b*DD + d] = va;
    } else {
        int bb = b - BB*TT;
        int t = threadIdx.x;
        if (t < 9) {
            int i = t / 3, k2 = t % 3;
            const float* L = lat + bb*9;
            g_lip[bb*9 + t] = L[i*3+0]*L[k2*3+0] + L[i*3+1]*L[k2*3+1] + L[i*3+2]*L[k2*3+2];
        }
    }
}

// ---------------- kernel 1b: convert+transpose weights to fp16 [N][K] ----------------
__global__ void convw_kernel(const float* __restrict__ ew1, const float* __restrict__ ew2,
                             const float* __restrict__ nw1, const float* __restrict__ nw2)
{
    int idx = blockIdx.x * 256 + threadIdx.x;
    if (idx < DD*272) {
        int n = idx / 272, k = idx % 272;
        g_ew1T[idx] = (k < 268) ? __float2half(ew1[k*DD + n]) : __half(0.f);
    } else if (idx < DD*272 + DD*DD) {
        int j = idx - DD*272;
        int n = j / DD, k = j % DD;
        g_ew2T[j] = __float2half(ew2[k*DD + n]);
    } else if (idx < DD*272 + DD*DD + DD*256) {
        int j = idx - DD*272 - DD*DD;
        int n = j / 256, k = j % 256;
        g_nw1T[j] = __float2half(nw1[k*DD + n]);
    } else if (idx < DD*272 + 2*DD*DD + DD*256) {
        int j = idx - DD*272 - DD*DD - DD*256;
        int n = j / DD, k = j % DD;
        g_nw2T[j] = __float2half(nw2[k*DD + n]);
    }
}

// ---------------- kernel 2: zero scatter buffers ----------------
__global__ void zero_kernel()
{
    int idx = blockIdx.x * blockDim.x + threadIdx.x;
    if (idx < NN*DD) g_agg[idx] = 0.f;
    if (idx < NN)    g_cnt[idx] = 0;
}

// ---------------- kernel 3: cross-attention (tf32 mma), writes g_h16 ----------------
#define AT 64
#define SAH 132

__global__ __launch_bounds__(256, 2)
void attn_kernel(const float* __restrict__ nfeat, const float* __restrict__ frac,
                 const int* __restrict__ n2g,
                 const float* __restrict__ wq, const float* __restrict__ bq,
                 const float* __restrict__ wo, const float* __restrict__ bo,
                 const float* __restrict__ sw1, const float* __restrict__ sb1,
                 const float* __restrict__ sw2, const float* __restrict__ sb2)
{
    extern __shared__ float sm[];
    float* s_h   = sm;
    float* s_q   = s_h + AT*SAH;
    float* s_bb  = s_q + AT*SAH;
    float* s_sw1 = s_bb + 2*BBF;
    float* s_sw2 = s_sw1 + 3072;
    float* s_sb1 = s_sw2 + 1024;
    float* s_sb2 = s_sb1 + 128;
    float* s_enc = s_sb2 + 8;
    float* s_att = s_enc + AT*24;
    __shared__ int s_g[AT];

    int tid = threadIdx.x, lane = tid & 31, wid = tid >> 5;
    int wm = wid >> 2, wn = wid & 3;
    int n0 = blockIdx.x * AT;
    int brow = tid >> 5, bc4 = (tid & 31) * 4;

    if (tid < AT) s_g[tid] = n2g[min(n0 + tid, NN - 1)];

    #pragma unroll
    for (int it = 0; it < 8; it++) {
        int idx = tid + it*256;
        int r = idx >> 5, c4 = (idx & 31) * 4;
        int n = min(n0 + r, NN - 1);
        cpa16(s_h + r*SAH + c4, nfeat + (size_t)n*DD + c4);
    }
    #pragma unroll
    for (int it = 0; it < 3; it++) {
        int idx = tid + it*256;
        cpa16(s_sw1 + idx*4, sw1 + idx*4);
    }
    cpa16(s_sw2 + tid*4, sw2 + tid*4);
    if (tid < 32) cpa16(s_sb1 + tid*4, sb1 + tid*4);
    if (tid < 2)  cpa16(s_sb2 + tid*4, sb2 + tid*4);
    cpa16(s_bb + brow*SB + bc4, wq + (size_t)brow*DD + bc4);
    cpa16(s_bb + (brow+8)*SB + bc4, wq + (size_t)(brow+8)*DD + bc4);
    CP_COMMIT;

    {
        int n = tid >> 2, sub = tid & 3;
        int nn = min(n0 + n, NN - 1);
        float f0 = frac[nn*3+0], f1 = frac[nn*3+1], f2 = frac[nn*3+2];
        #pragma unroll
        for (int k = sub; k < 24; k += 4) {
            int ii = k % 12, c = ii >> 2, j = ii & 3;
            float fv = (c == 0) ? f0 : ((c == 1) ? f1 : f2);
            float ph = fv * ((float)(1 << j) * 3.14159265358979323846f);
            s_enc[n*24 + k] = (k < 12) ? sinf(ph) : cosf(ph);
        }
    }
    CP_WAIT0;
    __syncthreads();

    float acc[2][4][4];
    #pragma unroll
    for (int mf = 0; mf < 2; mf++)
        #pragma unroll
        for (int nf = 0; nf < 4; nf++)
            #pragma unroll
            for (int u = 0; u < 4; u++) acc[mf][nf][u] = 0.f;

    for (int ct = 0; ct < 8; ct++) {
        const float* wsrc = (ct < 7) ? (wq + (size_t)(ct*16 + 16)*DD) : wo;
        float* dbuf = s_bb + ((ct+1)&1)*BBF;
        cpa16(dbuf + brow*SB + bc4, wsrc + (size_t)brow*DD + bc4);
        cpa16(dbuf + (brow+8)*SB + bc4, wsrc + (size_t)(brow+8)*DD + bc4);
        CP_COMMIT;
        const float* bB = s_bb + (ct & 1)*BBF;
        #pragma unroll
        for (int kk = 0; kk < 16; kk += 8) {
            int kg = ct*16 + kk;
            uint32_t afr[2][4];
            #pragma unroll
            for (int mf = 0; mf < 2; mf++) LOAD_AFRAG(afr[mf], s_h, SAH, wm*32 + mf*16, kg);
            uint32_t bfr[4][2];
            #pragma unroll
            for (int nf = 0; nf < 4; nf++) LOAD_BFRAG(bfr[nf], bB, kk, wn*32 + nf*8);
            #pragma unroll
            for (int mf = 0; mf < 2; mf++)
                #pragma unroll
                for (int nf = 0; nf < 4; nf++)
                    mma_tf32(acc[mf][nf], afr[mf], bfr[nf]);
        }
        CP_WAIT0;
        __syncthreads();
    }
    #pragma unroll
    for (int mf = 0; mf < 2; mf++) {
        int r0 = wm*32 + mf*16 + (lane >> 2);
        #pragma unroll
        for (int nf = 0; nf < 4; nf++) {
            int n = wn*32 + nf*8 + (lane & 3)*2;
            float b0 = bq[n], b1 = bq[n + 1];
            s_q[r0*SAH + n]           = acc[mf][nf][0] + b0;
            s_q[r0*SAH + n + 1]       = acc[mf][nf][1] + b1;
            s_q[(r0 + 8)*SAH + n]     = acc[mf][nf][2] + b0;
            s_q[(r0 + 8)*SAH + n + 1] = acc[mf][nf][3] + b1;
            #pragma unroll
            for (int u = 0; u < 4; u++) acc[mf][nf][u] = 0.f;
        }
    }
    __syncthreads();

    {
        int n = tid >> 2, sub = tid & 3;
        int gg = s_g[n];
        float b8[8];
        #pragma unroll
        for (int t = 0; t < 8; t++) b8[t] = 0.f;
        const float* en = s_enc + n*24;
        for (int cc = 0; cc < 32; cc++) {
            int c = cc*4 + sub;
            float hid = s_sb1[c];
            #pragma unroll
            for (int k = 0; k < 24; k++) hid = fmaf(en[k], s_sw1[k*DD + c], hid);
            hid = silu_f(hid);
            #pragma unroll
            for (int t = 0; t < 8; t++) b8[t] = fmaf(hid, s_sw2[c*8 + t], b8[t]);
        }
        #pragma unroll
        for (int t = 0; t < 8; t++) {
            b8[t] += __shfl_xor_sync(0xffffffffu, b8[t], 1, 4);
            b8[t] += __shfl_xor_sync(0xffffffffu, b8[t], 2, 4);
        }
        int t0 = sub*2, t1 = t0 + 1;
        const float* K0 = g_KV + (size_t)(gg*TT + t0)*DD;
        const float* K1 = K0 + DD;
        const float* qq = s_q + n*SAH;
        float sc0 = 0.f, sc1 = 0.f;
        #pragma unroll 8
        for (int k = 0; k < DD; k++) {
            float qv = qq[k];
            sc0 = fmaf(qv, K0[k], sc0);
            sc1 = fmaf(qv, K1[k], sc1);
        }
        float v0 = sc0 * 0.08838834764831845f + b8[t0] + s_sb2[t0];
        float v1 = sc1 * 0.08838834764831845f + b8[t1] + s_sb2[t1];
        float m = fmaxf(v0, v1);
        m = fmaxf(m, __shfl_xor_sync(0xffffffffu, m, 1, 4));
        m = fmaxf(m, __shfl_xor_sync(0xffffffffu, m, 2, 4));
        float e0 = __expf(v0 - m), e1 = __expf(v1 - m);
        float s = e0 + e1;
        s += __shfl_xor_sync(0xffffffffu, s, 1, 4);
        s += __shfl_xor_sync(0xffffffffu, s, 2, 4);
        float inv = __fdividef(1.f, s);
        s_att[n*8 + t0] = e0 * inv;
        s_att[n*8 + t1] = e1 * inv;
    }
    __syncthreads();

    #pragma unroll
    for (int it = 0; it < 32; it++) {
        int idx = tid + it*256;
        int n = idx >> 7, c = idx & 127;
        const float* Vr = g_KV + KV_OFF + (size_t)s_g[n]*TT*DD + c;
        const float* at = s_att + n*8;
        float a = 0.f;
        #pragma unroll
        for (int t = 0; t < 8; t++) a = fmaf(at[t], Vr[t*DD], a);
        s_q[n*SAH + c] = a;
    }
    __syncthreads();

    for (int c = 0; c < 8; c++) {
        if (c < 7) {
            float* dbuf = s_bb + ((c+1)&1)*BBF;
            cpa16(dbuf + brow*SB + bc4, wo + (size_t)(c*16 + 16 + brow)*DD + bc4);
            cpa16(dbuf + (brow+8)*SB + bc4, wo + (size_t)(c*16 + 24 + brow)*DD + bc4);
            CP_COMMIT;
        }
        const float* bB = s_bb + (c & 1)*BBF;
        #pragma unroll
        for (int kk = 0; kk < 16; kk += 8) {
            int kg = c*16 + kk;
            uint32_t afr[2][4];
            #pragma unroll
            for (int mf = 0; mf < 2; mf++) LOAD_AFRAG(afr[mf], s_q, SAH, wm*32 + mf*16, kg);
            uint32_t bfr[4][2];
            #pragma unroll
            for (int nf = 0; nf < 4; nf++) LOAD_BFRAG(bfr[nf], bB, kk, wn*32 + nf*8);
            #pragma unroll
            for (int mf = 0; mf < 2; mf++)
                #pragma unroll
                for (int nf = 0; nf < 4; nf++)
                    mma_tf32(acc[mf][nf], afr[mf], bfr[nf]);
        }
        if (c < 7) { CP_WAIT0; }
        __syncthreads();
    }

    // epilogue: g_h16 = half(h + ca@wo + bo)
    #pragma unroll
    for (int mf = 0; mf < 2; mf++) {
        #pragma unroll
        for (int rr = 0; rr < 2; rr++) {
            int m = wm*32 + mf*16 + (lane >> 2) + rr*8;
            int n = n0 + m;
            if (n < NN) {
                __half* orow = g_h16 + (size_t)n*DD;
                const float* hrow = s_h + m*SAH;
                #pragma unroll
                for (int nf = 0; nf < 4; nf++) {
                    int col = wn*32 + nf*8 + (lane & 3)*2;
                    float v0 = hrow[col]     + acc[mf][nf][rr*2 + 0] + bo[col];
                    float v1 = hrow[col + 1] + acc[mf][nf][rr*2 + 1] + bo[col + 1];
                    *(__half2*)(orow + col) = __floats2half2_rn(v0, v1);
                }
            }
        }
    }
}

// ---------------- kernel 4: edge MLP, fp16 m16n8k16 ----------------
// Tile 128 edges x 128 outs, 8 warps (2 wm x 4 wn), warp tile 64x32 (mf=4, nf=4).
#define TM 128
#define SAh 280    // A stride halfs; bank step 12 -> conflict-free
#define SBh 24     // B stride halfs (16 k + 8 pad); bank step 12 -> conflict-free
#define BHB (128*SBh)

__global__ __launch_bounds__(256, 2)
void edge_kernel(const float* __restrict__ frac,
                 const int* __restrict__ edges, const int* __restrict__ e2g,
                 const float* __restrict__ eb1, const float* __restrict__ eb2)
{
    extern __shared__ __half smh[];
    __half* s_a  = smh;               // TM*SAh halfs
    __half* s_bb = smh + TM*SAh;      // 2*BHB halfs
    __shared__ int s_i[TM], s_j[TM];

    int tid  = threadIdx.x, lane = tid & 31, wid = tid >> 5;
    int wm = wid >> 2, wn = wid & 3;
    int e0 = blockIdx.x * TM;
    int bn = tid >> 1, bs = (tid & 1) * 8;   // B coop-load: row n, seg

    if (tid < TM) {
        s_i[tid] = edges[e0 + tid];
        s_j[tid] = edges[EE + e0 + tid];
    }
    if (tid >= 128 && tid < 256) {
        // nothing
    }
    __syncthreads();

    // async gather A rows (fp16, 16B = 8 halfs per seg; 128 edges x 2 rows x 16 segs)
    #pragma unroll
    for (int it = 0; it < 16; it++) {
        int idx = tid + it*256;
        int r = idx >> 4, seg = idx & 15;
        int e = r >> 1, p = r & 1;
        int node = p ? s_j[e] : s_i[e];
        cpa16(s_a + e*SAh + p*DD + seg*8, g_h16 + (size_t)node*DD + seg*8);
    }
    // ew1T chunk 0 -> buf0
    cpa16(s_bb + bn*SBh + bs, g_ew1T + bn*272 + bs);
    CP_COMMIT;

    // tail cols 256..279 (lip, fd, pad) + counts
    if (tid < TM) {
        int e = tid;
        const float* lp = g_lip + e2g[e0 + e]*9;
        #pragma unroll
        for (int u = 0; u < 9; u++) s_a[e*SAh + 256 + u] = __float2half(lp[u]);
        int ii = s_i[e], jj = s_j[e];
        #pragma unroll
        for (int c = 0; c < 3; c++) {
            float dd = frac[jj*3 + c] - frac[ii*3 + c];
            dd -= floorf(dd);
            s_a[e*SAh + 265 + c] = __float2half(dd);
        }
        #pragma unroll
        for (int u = 268; u < 280; u++) s_a[e*SAh + u] = __half(0.f);
        atomicAdd(&g_cnt[ii], 1);
    }

    float acc[4][4][4];
    #pragma unroll
    for (int mf = 0; mf < 4; mf++)
        #pragma unroll
        for (int nf = 0; nf < 4; nf++)
            #pragma unroll
            for (int u = 0; u < 4; u++) acc[mf][nf][u] = 0.f;

    CP_WAIT0;
    __syncthreads();

    // ---- GEMM1: K=272, 17 chunks of K=16 ----
    for (int ct = 0; ct < 17; ct++) {
        __half* dbuf = s_bb + ((ct+1)&1)*BHB;
        if (ct < 16) cpa16(dbuf + bn*SBh + bs, g_ew1T + bn*272 + (ct*16 + 16) + bs);
        else         cpa16(dbuf + bn*SBh + bs, g_ew2T + bn*128 + bs);
        CP_COMMIT;
        const __half* bB = s_bb + (ct & 1)*BHB;
        int kg = ct*16;
        uint32_t afr[4][4];
        #pragma unroll
        for (int mf = 0; mf < 4; mf++) LDA16(afr[mf], s_a, SAh, wm*64 + mf*16, kg);
        uint32_t bfr[4][2];
        #pragma unroll
        for (int nf = 0; nf < 4; nf++) LDB16(bfr[nf], bB, SBh, wn*32 + nf*8);
        #pragma unroll
        for (int mf = 0; mf < 4; mf++)
            #pragma unroll
            for (int nf = 0; nf < 4; nf++)
                mma_f16(acc[mf][nf], afr[mf], bfr[nf]);
        CP_WAIT0;
        __syncthreads();
    }

    // hidden = silu(acc + eb1) -> s_a cols 0..127 (half2 stores)
    #pragma unroll
    for (int mf = 0; mf < 4; mf++) {
        int r0 = wm*64 + mf*16 + (lane >> 2);
        #pragma unroll
        for (int nf = 0; nf < 4; nf++) {
            int n = wn*32 + nf*8 + (lane & 3)*2;
            float b0 = eb1[n], b1 = eb1[n + 1];
            *(__half2*)(s_a + r0*SAh + n) =
                __floats2half2_rn(silu_f(acc[mf][nf][0] + b0), silu_f(acc[mf][nf][1] + b1));
            *(__half2*)(s_a + (r0 + 8)*SAh + n) =
                __floats2half2_rn(silu_f(acc[mf][nf][2] + b0), silu_f(acc[mf][nf][3] + b1));
            #pragma unroll
            for (int u = 0; u < 4; u++) acc[mf][nf][u] = 0.f;
        }
    }
    __syncthreads();

    // ---- GEMM2: K=128, 8 chunks; chunk c in buf[(1+c)&1] ----
    for (int c = 0; c < 8; c++) {
        if (c < 7) {
            cpa16(s_bb + (c & 1)*BHB + bn*SBh + bs, g_ew2T + bn*128 + (c*16 + 16) + bs);
            CP_COMMIT;
        }
        const __half* bB = s_bb + ((1 + c) & 1)*BHB;
        int kg = c*16;
        uint32_t afr[4][4];
        #pragma unroll
        for (int mf = 0; mf < 4; mf++) LDA16(afr[mf], s_a, SAh, wm*64 + mf*16, kg);
        uint32_t bfr[4][2];
        #pragma unroll
        for (int nf = 0; nf < 4; nf++) LDB16(bfr[nf], bB, SBh, wn*32 + nf*8);
        #pragma unroll
        for (int mf = 0; mf < 4; mf++)
            #pragma unroll
            for (int nf = 0; nf < 4; nf++)
                mma_f16(acc[mf][nf], afr[mf], bfr[nf]);
        if (c < 7) { CP_WAIT0; }
        __syncthreads();
    }

    // epilogue: silu + bias, red.v2 scatter into g_agg (fp32)
    #pragma unroll
    for (int mf = 0; mf < 4; mf++) {
        #pragma unroll
        for (int rr = 0; rr < 2; rr++) {
            int m = wm*64 + mf*16 + (lane >> 2) + rr*8;
            float* ap = g_agg + (size_t)s_i[m]*DD;
            #pragma unroll
            for (int nf = 0; nf < 4; nf++) {
                int n = wn*32 + nf*8 + (lane & 3)*2;
                float v0 = silu_f(acc[mf][nf][rr*2 + 0] + eb2[n]);
                float v1 = silu_f(acc[mf][nf][rr*2 + 1] + eb2[n + 1]);
                asm volatile("red.global.add.v2.f32 [%0], {%1, %2};"
                             :: "l"(ap + n), "f"(v0), "f"(v1) : "memory");
            }
        }
    }
}

// ---------------- kernel 5: node MLP, fp16 m16n8k16 ----------------
#define TN 128
#define SAn 264    // bank step 4 -> conflict-free

__global__ __launch_bounds__(256, 2)
void node_kernel(const float* __restrict__ nfeat,
                 const float* __restrict__ nb1, const float* __restrict__ nb2,
                 float* __restrict__ out)
{
    extern __shared__ __half smh[];
    __half* s_a  = smh;               // TN*SAn
    __half* s_bb = smh + TN*SAn;      // 2*BHB
    __shared__ float s_cnt[TN];

    int tid  = threadIdx.x, lane = tid & 31, wid = tid >> 5;
    int wm = wid >> 2, wn = wid & 3;
    int n0 = blockIdx.x * TN;
    int bn = tid >> 1, bs = (tid & 1) * 8;

    if (tid < TN) {
        int n = min(n0 + tid, NN - 1);
        s_cnt[tid] = fmaxf((float)g_cnt[n], 1.f);
    }
    // h rows (fp16 direct)
    #pragma unroll
    for (int it = 0; it < 8; it++) {
        int idx = tid + it*256;
        int r = idx >> 4, seg = idx & 15;
        int n = min(n0 + r, NN - 1);
        cpa16(s_a + r*SAn + seg*8, g_h16 + (size_t)n*DD + seg*8);
    }
    cpa16(s_bb + bn*SBh + bs, g_nw1T + bn*256 + bs);
    CP_COMMIT;
    __syncthreads();   // s_cnt visible

    // agg/cnt -> cols 128..255 (fp32 load, convert)
    #pragma unroll
    for (int it = 0; it < 16; it++) {
        int idx = tid + it*256;
        int r = idx >> 5, c4 = (idx & 31) * 4;
        int n = min(n0 + r, NN - 1);
        float inv = __fdividef(1.f, s_cnt[r]);
        float4 v = *(const float4*)(g_agg + (size_t)n*DD + c4);
        __half* dst = s_a + r*SAn + DD + c4;
        *(__half2*)(dst)     = __floats2half2_rn(v.x * inv, v.y * inv);
        *(__half2*)(dst + 2) = __floats2half2_rn(v.z * inv, v.w * inv);
    }

    float acc[4][4][4];
    #pragma unroll
    for (int mf = 0; mf < 4; mf++)
        #pragma unroll
        for (int nf = 0; nf < 4; nf++)
            #pragma unroll
            for (int u = 0; u < 4; u++) acc[mf][nf][u] = 0.f;

    CP_WAIT0;
    __syncthreads();

    // ---- GEMM1: K=256, 16 chunks ----
    for (int ct = 0; ct < 16; ct++) {
        __half* dbuf = s_bb + ((ct+1)&1)*BHB;
        if (ct < 15) cpa16(dbuf + bn*SBh + bs, g_nw1T + bn*256 + (ct*16 + 16) + bs);
        else         cpa16(dbuf + bn*SBh + bs, g_nw2T + bn*128 + bs);
        CP_COMMIT;
        const __half* bB = s_bb + (ct & 1)*BHB;
        int kg = ct*16;
        uint32_t afr[4][4];
        #pragma unroll
        for (int mf = 0; mf < 4; mf++) LDA16(afr[mf], s_a, SAn, wm*64 + mf*16, kg);
        uint32_t bfr[4][2];
        #pragma unroll
        for (int nf = 0; nf < 4; nf++) LDB16(bfr[nf], bB, SBh, wn*32 + nf*8);
        #pragma unroll
        for (int mf = 0; mf < 4; mf++)
            #pragma unroll
            for (int nf = 0; nf < 4; nf++)
                mma_f16(acc[mf][nf], afr[mf], bfr[nf]);
        CP_WAIT0;
        __syncthreads();
    }

    // hidden -> s_a cols 0..127
    #pragma unroll
    for (int mf = 0; mf < 4; mf++) {
        int r0 = wm*64 + mf*16 + (lane >> 2);
        #pragma unroll
        for (int nf = 0; nf < 4; nf++) {
            int n = wn*32 + nf*8 + (lane & 3)*2;
            float b0 = nb1[n], b1 = nb1[n + 1];
            *(__half2*)(s_a + r0*SAn + n) =
                __floats2half2_rn(silu_f(acc[mf][nf][0] + b0), silu_f(acc[mf][nf][1] + b1));
            *(__half2*)(s_a + (r0 + 8)*SAn + n) =
                __floats2half2_rn(silu_f(acc[mf][nf][2] + b0), silu_f(acc[mf][nf][3] + b1));
            #pragma unroll
            for (int u = 0; u < 4; u++) acc[mf][nf][u] = 0.f;
        }
    }
    __syncthreads();

    // ---- GEMM2: K=128, 8 chunks; chunk c in buf[c&1] ----
    for (int c = 0; c < 8; c++) {
        if (c < 7) {
            cpa16(s_bb + ((c+1)&1)*BHB + bn*SBh + bs, g_nw2T + bn*128 + (c*16 + 16) + bs);
            CP_COMMIT;
        }
        const __half* bB = s_bb + (c & 1)*BHB;
        int kg = c*16;
        uint32_t afr[4][4];
        #pragma unroll
        for (int mf = 0; mf < 4; mf++) LDA16(afr[mf], s_a, SAn, wm*64 + mf*16, kg);
        uint32_t bfr[4][2];
        #pragma unroll
        for (int nf = 0; nf < 4; nf++) LDB16(bfr[nf], bB, SBh, wn*32 + nf*8);
        #pragma unroll
        for (int mf = 0; mf < 4; mf++)
            #pragma unroll
            for (int nf = 0; nf < 4; nf++)
                mma_f16(acc[mf][nf], afr[mf], bfr[nf]);
        if (c < 7) { CP_WAIT0; }
        __syncthreads();
    }

    // epilogue: out = nfeat + silu(acc + nb2)
    #pragma unroll
    for (int mf = 0; mf < 4; mf++) {
        #pragma unroll
        for (int rr = 0; rr < 2; rr++) {
            int m = wm*64 + mf*16 + (lane >> 2) + rr*8;
            int n = n0 + m;
            if (n < NN) {
                const float* nfr = nfeat + (size_t)n*DD;
                float* orow = out + (size_t)n*DD;
                #pragma unroll
                for (int nf = 0; nf < 4; nf++) {
                    int col = wn*32 + nf*8 + (lane & 3)*2;
                    orow[col]     = nfr[col]     + silu_f(acc[mf][nf][rr*2 + 0] + nb2[col]);
                    orow[col + 1] = nfr[col + 1] + silu_f(acc[mf][nf][rr*2 + 1] + nb2[col + 1]);
                }
            }
        }
    }
}

// ---------------- launch ----------------
extern "C" void kernel_launch(void* const* d_in, const int* in_sizes, int n_in,
                              void* d_out, int out_size)
{
    const float* node_features = (const float*)d_in[0];
    const float* cond = (const float*)d_in[1];
    const int*   n2g  = (const int*)d_in[2];
    const float* frac = (const float*)d_in[3];
    const float* lat  = (const float*)d_in[4];
    const int*   edges= (const int*)d_in[5];
    const int*   e2g  = (const int*)d_in[6];
    const float* wq = (const float*)d_in[7];
    const float* bq = (const float*)d_in[8];
    const float* wk = (const float*)d_in[9];
    const float* bk = (const float*)d_in[10];
    const float* wv = (const float*)d_in[11];
    const float* bv = (const float*)d_in[12];
    const float* wo = (const float*)d_in[13];
    const float* bo = (const float*)d_in[14];
    const float* sw1= (const float*)d_in[15];
    const float* sb1= (const float*)d_in[16];
    const float* sw2= (const float*)d_in[17];
    const float* sb2= (const float*)d_in[18];
    const float* ew1= (const float*)d_in[19];
    const float* eb1= (const float*)d_in[20];
    const float* ew2= (const float*)d_in[21];
    const float* eb2= (const float*)d_in[22];
    const float* nw1= (const float*)d_in[23];
    const float* nb1= (const float*)d_in[24];
    const float* nw2= (const float*)d_in[25];
    const float* nb2= (const float*)d_in[26];
    float* out = (float*)d_out;

    const int attn_smem = (2*AT*SAH + 2*BBF + 3072 + 1024 + 128 + 8 + AT*24 + AT*8) * 4;
    const int edge_smem = (TM*SAh + 2*BHB) * 2;   // halfs
    const int node_smem = (TN*SAn + 2*BHB) * 2;
    cudaFuncSetAttribute(attn_kernel, cudaFuncAttributeMaxDynamicSharedMemorySize, attn_smem);
    cudaFuncSetAttribute(edge_kernel, cudaFuncAttributeMaxDynamicSharedMemorySize, edge_smem);
    cudaFuncSetAttribute(node_kernel, cudaFuncAttributeMaxDynamicSharedMemorySize, node_smem);

    prep_kernel<<<BB*TT + BB, 128>>>(cond, wk, bk, wv, bv, lat);
    convw_kernel<<<(DD*272 + 2*DD*DD + DD*256 + 255)/256, 256>>>(ew1, ew2, nw1, nw2);
    zero_kernel<<<(NN*DD + 255) / 256, 256>>>();
    attn_kernel<<<(NN + AT - 1) / AT, 256, attn_smem>>>(node_features, frac, n2g,
                                                        wq, bq, wo, bo, sw1, sb1, sw2, sb2);
    edge_kernel<<<EE / TM, 256, edge_smem>>>(frac, edges, e2g, eb1, eb2);
    node_kernel<<<(NN + TN - 1) / TN, 256, node_smem>>>(node_features, nb1, nb2, out);
}

// round 10
// speedup vs baseline: 1.0629x; 1.0629x over previous
#include <cuda_runtime.h>
#include <cuda_fp16.h>
#include <math.h>
#include <stdint.h>

#define NN 50000
#define EE 800000
#define BB 256
#define DD 128
#define TT 8
#define KV_OFF (BB*TT*DD)

// ---------------- scratch (no allocations allowed) ----------------
__device__ __half g_h16[(size_t)NN*DD];     // post-attention node states (fp16)
__device__ float  g_KV[2*BB*TT*DD];         // Kc then Vc (fp32)
__device__ float  g_lip[BB*9];              // lattice inner products
__device__ float  g_agg[(size_t)NN*DD];     // scatter sums (fp32 atomics)
__device__ int    g_cnt[NN];                // scatter counts
// pre-converted, pre-transposed fp16 weights [N][K]
__device__ __half g_ew1T[DD*288];           // K padded 272->288
__device__ __half g_ew2T[DD*DD];
__device__ __half g_nw1T[DD*256];
__device__ __half g_nw2T[DD*DD];
__device__ __half g_wqT[DD*DD];
__device__ __half g_woT[DD*DD];
__device__ __half g_sw1T[DD*32];            // K padded 24->32

__device__ __forceinline__ float silu_f(float x) {
    return __fdividef(x, 1.f + __expf(-x));
}

// fp16 mma, fp32 accumulate
__device__ __forceinline__ void mma_f16(float* c, const uint32_t* a, const uint32_t* b) {
    asm volatile(
        "mma.sync.aligned.m16n8k16.row.col.f32.f16.f16.f32 "
        "{%0,%1,%2,%3}, {%4,%5,%6,%7}, {%8,%9}, {%0,%1,%2,%3};\n"
        : "+f"(c[0]), "+f"(c[1]), "+f"(c[2]), "+f"(c[3])
        : "r"(a[0]), "r"(a[1]), "r"(a[2]), "r"(a[3]), "r"(b[0]), "r"(b[1]));
}

__device__ __forceinline__ void cpa16(void* dst, const void* src) {
    uint32_t d = (uint32_t)__cvta_generic_to_shared(dst);
    asm volatile("cp.async.cg.shared.global [%0], [%1], 16;" :: "r"(d), "l"(src));
}
#define CP_COMMIT asm volatile("cp.async.commit_group;" ::: "memory")
#define CP_WAIT0  asm volatile("cp.async.wait_group 0;" ::: "memory")

// B buffer geometry: 128 n-rows x (32 k + 8 pad) halfs
#define SBh 40
#define BHB (128*SBh)

// -------- fp16 fragment loads (A row-major [m][k], B as [n][k]) --------
#define LDA16(afr, base, SAx, rowbase, kg)                                        \
    {                                                                             \
        const __half* ap_ = (base) + ((rowbase) + (lane >> 2))*(SAx) + (kg) + ((lane & 3)*2); \
        afr[0] = *(const uint32_t*)(ap_);                                         \
        afr[1] = *(const uint32_t*)(ap_ + 8*(SAx));                               \
        afr[2] = *(const uint32_t*)(ap_ + 8);                                     \
        afr[3] = *(const uint32_t*)(ap_ + 8*(SAx) + 8);                           \
    }
#define LDB16K(bfr, bB, SBx, ncol, kk)                                            \
    {                                                                             \
        const __half* bp_ = (bB) + ((ncol) + (lane >> 2))*(SBx) + (kk) + ((lane & 3)*2); \
        bfr[0] = *(const uint32_t*)(bp_);                                         \
        bfr[1] = *(const uint32_t*)(bp_ + 8);                                     \
    }

// ---------------- kernel 1: K/V projection + lattice gram ----------------
__global__ void prep_kernel(const float* __restrict__ cond,
                            const float* __restrict__ wk, const float* __restrict__ bk,
                            const float* __restrict__ wv, const float* __restrict__ bv,
                            const float* __restrict__ lat)
{
    int b = blockIdx.x;
    if (b < BB*TT) {
        __shared__ float s_c[DD];
        int d = threadIdx.x;
        s_c[d] = cond[b*DD + d];
        __syncthreads();
        float ka = bk[d], va = bv[d];
        #pragma unroll 8
        for (int k = 0; k < DD; k++) {
            float c = s_c[k];
            ka = fmaf(c, wk[k*DD + d], ka);
            va = fmaf(c, wv[k*DD + d], va);
        }
        g_KV[b*DD + d] = ka;
        g_KV[KV_OFF + b*DD + d] = va;
    } else {
        int bb = b - BB*TT;
        int t = threadIdx.x;
        if (t < 9) {
            int i = t / 3, k2 = t % 3;
            const float* L = lat + bb*9;
            g_lip[bb*9 + t] = L[i*3+0]*L[k2*3+0] + L[i*3+1]*L[k2*3+1] + L[i*3+2]*L[k2*3+2];
        }
    }
}

// ---------------- kernel 1b: convert+transpose weights to fp16 [N][K] ----------------
// ranges (cumulative): ew1T 36864 | ew2T 53248 | nw1T 86016 | nw2T 102400
//                      wqT 118784 | woT 135168 | sw1T 139264
__global__ void convw_kernel(const float* __restrict__ ew1, const float* __restrict__ ew2,
                             const float* __restrict__ nw1, const float* __restrict__ nw2,
                             const float* __restrict__ wq,  const float* __restrict__ wo,
                             const float* __restrict__ sw1)
{
    int idx = blockIdx.x * 256 + threadIdx.x;
    if (idx < 36864) {
        int n = idx / 288, k = idx % 288;
        g_ew1T[idx] = (k < 268) ? __float2half(ew1[k*DD + n]) : __half(0.f);
    } else if (idx < 53248) {
        int j = idx - 36864; int n = j / DD, k = j % DD;
        g_ew2T[j] = __float2half(ew2[k*DD + n]);
    } else if (idx < 86016) {
        int j = idx - 53248; int n = j / 256, k = j % 256;
        g_nw1T[j] = __float2half(nw1[k*DD + n]);
    } else if (idx < 102400) {
        int j = idx - 86016; int n = j / DD, k = j % DD;
        g_nw2T[j] = __float2half(nw2[k*DD + n]);
    } else if (idx < 118784) {
        int j = idx - 102400; int n = j / DD, k = j % DD;
        g_wqT[j] = __float2half(wq[k*DD + n]);
    } else if (idx < 135168) {
        int j = idx - 118784; int n = j / DD, k = j % DD;
        g_woT[j] = __float2half(wo[k*DD + n]);
    } else if (idx < 139264) {
        int j = idx - 135168; int n = j / 32, k = j % 32;
        g_sw1T[j] = (k < 24) ? __float2half(sw1[k*DD + n]) : __half(0.f);
    }
}

// ---------------- kernel 2: zero scatter buffers ----------------
__global__ void zero_kernel()
{
    int idx = blockIdx.x * blockDim.x + threadIdx.x;
    if (idx < NN*DD) g_agg[idx] = 0.f;
    if (idx < NN)    g_cnt[idx] = 0;
}

// ---------------- kernel 3: cross-attention, fp16 mma ----------------
// Tile 64 nodes, 8 warps (2 wm x 4 wn), warp tile 32x32 (mf=2, nf=4).
#define AT 64
#define SQh 136    // h/q/ca tile stride (halfs); bank step 4 -> conflict-free

__global__ __launch_bounds__(256, 2)
void attn_kernel(const float* __restrict__ nfeat, const float* __restrict__ frac,
                 const int* __restrict__ n2g,
                 const float* __restrict__ bq, const float* __restrict__ bo,
                 const float* __restrict__ sb1,
                 const float* __restrict__ sw2, const float* __restrict__ sb2)
{
    extern __shared__ char smraw[];
    __half* s_h   = (__half*)smraw;                 // 64*136 h          17408 B
    __half* s_hid = s_h + AT*SQh;                   // 64*136 hidden     17408 B
    __half* s_q   = s_hid + AT*SQh;                 // 64*136 q/ca       17408 B
    __half* s_bsw = s_q + AT*SQh;                   // 128*40 sw1T       10240 B
    __half* s_bb  = s_bsw + 128*SBh;                // 2*BHB             20480 B
    float*  s_sw2 = (float*)(s_bb + 2*BHB);         // 1024 f             4096 B
    float*  s_sb1 = s_sw2 + 1024;                   // 128 f               512 B
    float*  s_sb2 = s_sb1 + 128;                    // 8 f                  32 B
    __half* s_enc = (__half*)(s_sb2 + 8);           // 64*40 enc          5120 B
    float*  s_att = (float*)(s_enc + AT*40);        // 64*8               2048 B
    __shared__ int s_g[AT];

    int tid = threadIdx.x, lane = tid & 31, wid = tid >> 5;
    int wm = wid >> 2, wn = wid & 3;
    int n0 = blockIdx.x * AT;
    int bn = tid >> 1, bseg = (tid & 1) * 16;

    if (tid < AT) s_g[tid] = n2g[min(n0 + tid, NN - 1)];

    // async: sw1T tile, sw2, sb1, sb2, wqT chunk0
    cpa16(s_bsw + bn*SBh + bseg,     g_sw1T + bn*32 + bseg);
    cpa16(s_bsw + bn*SBh + bseg + 8, g_sw1T + bn*32 + bseg + 8);
    cpa16(s_sw2 + tid*4, sw2 + tid*4);
    if (tid < 32) cpa16(s_sb1 + tid*4, sb1 + tid*4);
    if (tid < 2)  cpa16(s_sb2 + tid*4, sb2 + tid*4);
    cpa16(s_bb + bn*SBh + bseg,     g_wqT + bn*DD + bseg);
    cpa16(s_bb + bn*SBh + bseg + 8, g_wqT + bn*DD + bseg + 8);
    CP_COMMIT;

    // h tile: fp32 load + fp16 convert (2048 float4 / 256 thr = 8 iters)
    #pragma unroll
    for (int it = 0; it < 8; it++) {
        int idx = tid + it*256;
        int r = idx >> 5, c4 = (idx & 31) * 4;
        int n = min(n0 + r, NN - 1);
        float4 v = *(const float4*)(nfeat + (size_t)n*DD + c4);
        __half* dst = s_h + r*SQh + c4;
        *(__half2*)(dst)     = __floats2half2_rn(v.x, v.y);
        *(__half2*)(dst + 2) = __floats2half2_rn(v.z, v.w);
    }
    // enc: thread = (node, sub)
    {
        int n = tid >> 2, sub = tid & 3;
        int nn = min(n0 + n, NN - 1);
        float f0 = frac[nn*3+0], f1 = frac[nn*3+1], f2 = frac[nn*3+2];
        #pragma unroll
        for (int k = sub; k < 24; k += 4) {
            int ii = k % 12, c = ii >> 2, j = ii & 3;
            float fv = (c == 0) ? f0 : ((c == 1) ? f1 : f2);
            float ph = fv * ((float)(1 << j) * 3.14159265358979323846f);
            s_enc[n*40 + k] = __float2half((k < 12) ? sinf(ph) : cosf(ph));
        }
        s_enc[n*40 + 24 + sub] = __half(0.f);
        s_enc[n*40 + 28 + sub] = __half(0.f);
    }
    CP_WAIT0;
    __syncthreads();

    float acc[2][4][4];
    #pragma unroll
    for (int mf = 0; mf < 2; mf++)
        #pragma unroll
        for (int nf = 0; nf < 4; nf++)
            #pragma unroll
            for (int u = 0; u < 4; u++) acc[mf][nf][u] = 0.f;

    // ---- bias GEMM: hidden = silu(enc @ sw1 + sb1), one K=32 round ----
    #pragma unroll
    for (int kk = 0; kk < 32; kk += 16) {
        uint32_t afr[2][4];
        #pragma unroll
        for (int mf = 0; mf < 2; mf++) LDA16(afr[mf], s_enc, 40, wm*32 + mf*16, kk);
        uint32_t bfr[4][2];
        #pragma unroll
        for (int nf = 0; nf < 4; nf++) LDB16K(bfr[nf], s_bsw, SBh, wn*32 + nf*8, kk);
        #pragma unroll
        for (int mf = 0; mf < 2; mf++)
            #pragma unroll
            for (int nf = 0; nf < 4; nf++)
                mma_f16(acc[mf][nf], afr[mf], bfr[nf]);
    }
    #pragma unroll
    for (int mf = 0; mf < 2; mf++) {
        int r0 = wm*32 + mf*16 + (lane >> 2);
        #pragma unroll
        for (int nf = 0; nf < 4; nf++) {
            int n = wn*32 + nf*8 + (lane & 3)*2;
            float b0 = s_sb1[n], b1 = s_sb1[n + 1];
            *(__half2*)(s_hid + r0*SQh + n) =
                __floats2half2_rn(silu_f(acc[mf][nf][0] + b0), silu_f(acc[mf][nf][1] + b1));
            *(__half2*)(s_hid + (r0 + 8)*SQh + n) =
                __floats2half2_rn(silu_f(acc[mf][nf][2] + b0), silu_f(acc[mf][nf][3] + b1));
            #pragma unroll
            for (int u = 0; u < 4; u++) acc[mf][nf][u] = 0.f;
        }
    }

    // ---- GEMM Q = h @ wq: 4 rounds of K=32 ----
    for (int ct = 0; ct < 4; ct++) {
        __half* dbuf = s_bb + ((ct+1)&1)*BHB;
        const __half* src = (ct < 3) ? (g_wqT + (ct+1)*32) : g_woT;
        cpa16(dbuf + bn*SBh + bseg,     src + bn*DD + bseg);
        cpa16(dbuf + bn*SBh + bseg + 8, src + bn*DD + bseg + 8);
        CP_COMMIT;
        const __half* bB = s_bb + (ct & 1)*BHB;
        #pragma unroll
        for (int kk = 0; kk < 32; kk += 16) {
            int kg = ct*32 + kk;
            uint32_t afr[2][4];
            #pragma unroll
            for (int mf = 0; mf < 2; mf++) LDA16(afr[mf], s_h, SQh, wm*32 + mf*16, kg);
            uint32_t bfr[4][2];
            #pragma unroll
            for (int nf = 0; nf < 4; nf++) LDB16K(bfr[nf], bB, SBh, wn*32 + nf*8, kk);
            #pragma unroll
            for (int mf = 0; mf < 2; mf++)
                #pragma unroll
                for (int nf = 0; nf < 4; nf++)
                    mma_f16(acc[mf][nf], afr[mf], bfr[nf]);
        }
        CP_WAIT0;
        __syncthreads();
    }
    #pragma unroll
    for (int mf = 0; mf < 2; mf++) {
        int r0 = wm*32 + mf*16 + (lane >> 2);
        #pragma unroll
        for (int nf = 0; nf < 4; nf++) {
            int n = wn*32 + nf*8 + (lane & 3)*2;
            float b0 = bq[n], b1 = bq[n + 1];
            *(__half2*)(s_q + r0*SQh + n) =
                __floats2half2_rn(acc[mf][nf][0] + b0, acc[mf][nf][1] + b1);
            *(__half2*)(s_q + (r0 + 8)*SQh + n) =
                __floats2half2_rn(acc[mf][nf][2] + b0, acc[mf][nf][3] + b1);
            #pragma unroll
            for (int u = 0; u < 4; u++) acc[mf][nf][u] = 0.f;
        }
    }
    __syncthreads();

    // ---- scores + spatial bias + softmax: thread = (node, sub of 4) ----
    {
        int n = tid >> 2, sub = tid & 3;
        int gg = s_g[n];
        int t0 = sub*2, t1 = t0 + 1;
        const float* K0 = g_KV + (size_t)(gg*TT + t0)*DD;
        const float* K1 = K0 + DD;
        const __half* qq = s_q + n*SQh;
        const __half* hh = s_hid + n*SQh;
        float sc0 = 0.f, sc1 = 0.f, bi0 = 0.f, bi1 = 0.f;
        #pragma unroll 8
        for (int k = 0; k < DD; k++) {
            float qv = __half2float(qq[k]);
            sc0 = fmaf(qv, K0[k], sc0);
            sc1 = fmaf(qv, K1[k], sc1);
            float hv = __half2float(hh[k]);
            bi0 = fmaf(hv, s_sw2[k*8 + t0], bi0);
            bi1 = fmaf(hv, s_sw2[k*8 + t1], bi1);
        }
        float v0 = sc0 * 0.08838834764831845f + bi0 + s_sb2[t0];
        float v1 = sc1 * 0.08838834764831845f + bi1 + s_sb2[t1];
        float m = fmaxf(v0, v1);
        m = fmaxf(m, __shfl_xor_sync(0xffffffffu, m, 1, 4));
        m = fmaxf(m, __shfl_xor_sync(0xffffffffu, m, 2, 4));
        float e0 = __expf(v0 - m), e1 = __expf(v1 - m);
        float s = e0 + e1;
        s += __shfl_xor_sync(0xffffffffu, s, 1, 4);
        s += __shfl_xor_sync(0xffffffffu, s, 2, 4);
        float inv = __fdividef(1.f, s);
        s_att[n*8 + t0] = e0 * inv;
        s_att[n*8 + t1] = e1 * inv;
    }
    __syncthreads();

    // ---- ca = attn @ V -> s_q (fp16) ----
    #pragma unroll
    for (int it = 0; it < 16; it++) {
        int idx = tid + it*256;
        int n = idx >> 6, c = (idx & 63) * 2;
        const float* Vr = g_KV + KV_OFF + (size_t)s_g[n]*TT*DD + c;
        const float* at = s_att + n*8;
        float a0 = 0.f, a1 = 0.f;
        #pragma unroll
        for (int t = 0; t < 8; t++) {
            a0 = fmaf(at[t], Vr[t*DD],     a0);
            a1 = fmaf(at[t], Vr[t*DD + 1], a1);
        }
        *(__half2*)(s_q + n*SQh + c) = __floats2half2_rn(a0, a1);
    }
    __syncthreads();

    // ---- GEMM out = ca @ wo: 4 rounds (chunk0 already in buf0) ----
    for (int c = 0; c < 4; c++) {
        if (c < 3) {
            __half* dbuf = s_bb + ((c+1)&1)*BHB;
            const __half* src = g_woT + (c+1)*32;
            cpa16(dbuf + bn*SBh + bseg,     src + bn*DD + bseg);
            cpa16(dbuf + bn*SBh + bseg + 8, src + bn*DD + bseg + 8);
            CP_COMMIT;
        }
        const __half* bB = s_bb + (c & 1)*BHB;
        #pragma unroll
        for (int kk = 0; kk < 32; kk += 16) {
            int kg = c*32 + kk;
            uint32_t afr[2][4];
            #pragma unroll
            for (int mf = 0; mf < 2; mf++) LDA16(afr[mf], s_q, SQh, wm*32 + mf*16, kg);
            uint32_t bfr[4][2];
            #pragma unroll
            for (int nf = 0; nf < 4; nf++) LDB16K(bfr[nf], bB, SBh, wn*32 + nf*8, kk);
            #pragma unroll
            for (int mf = 0; mf < 2; mf++)
                #pragma unroll
                for (int nf = 0; nf < 4; nf++)
                    mma_f16(acc[mf][nf], afr[mf], bfr[nf]);
        }
        if (c < 3) { CP_WAIT0; }
        __syncthreads();
    }

    // epilogue: g_h16 = half(h + ca@wo + bo)
    #pragma unroll
    for (int mf = 0; mf < 2; mf++) {
        #pragma unroll
        for (int rr = 0; rr < 2; rr++) {
            int m = wm*32 + mf*16 + (lane >> 2) + rr*8;
            int n = n0 + m;
            if (n < NN) {
                __half* orow = g_h16 + (size_t)n*DD;
                const __half* hrow = s_h + m*SQh;
                #pragma unroll
                for (int nf = 0; nf < 4; nf++) {
                    int col = wn*32 + nf*8 + (lane & 3)*2;
                    float v0 = __half2float(hrow[col])     + acc[mf][nf][rr*2 + 0] + bo[col];
                    float v1 = __half2float(hrow[col + 1]) + acc[mf][nf][rr*2 + 1] + bo[col + 1];
                    *(__half2*)(orow + col) = __floats2half2_rn(v0, v1);
                }
            }
        }
    }
}

// ---------------- kernel 4: edge MLP, fp16, K=32 rounds ----------------
// Tile 128 edges x 128 outs, 8 warps (2 wm x 4 wn), warp tile 64x32 (mf=4, nf=4).
#define TM 128
#define SAh 296    // A stride halfs (288 k + 8 pad); conflict-free

__global__ __launch_bounds__(256, 2)
void edge_kernel(const float* __restrict__ frac,
                 const int* __restrict__ edges, const int* __restrict__ e2g,
                 const float* __restrict__ eb1, const float* __restrict__ eb2)
{
    extern __shared__ __half smh[];
    __half* s_a  = smh;               // TM*SAh halfs (75776 B)
    __half* s_bb = smh + TM*SAh;      // 2*BHB halfs  (20480 B)
    __shared__ int s_i[TM], s_j[TM];

    int tid  = threadIdx.x, lane = tid & 31, wid = tid >> 5;
    int wm = wid >> 2, wn = wid & 3;
    int e0 = blockIdx.x * TM;
    int bn = tid >> 1, bseg = (tid & 1) * 16;

    if (tid < TM) {
        s_i[tid] = edges[e0 + tid];
        s_j[tid] = edges[EE + e0 + tid];
    }
    __syncthreads();

    // async gather A rows (128 edges x 2 nodes x 16 segs of 8 halfs)
    #pragma unroll
    for (int it = 0; it < 16; it++) {
        int idx = tid + it*256;
        int r = idx >> 4, seg = idx & 15;
        int e = r >> 1, p = r & 1;
        int node = p ? s_j[e] : s_i[e];
        cpa16(s_a + e*SAh + p*DD + seg*8, g_h16 + (size_t)node*DD + seg*8);
    }
    // ew1T chunk 0 -> buf0
    cpa16(s_bb + bn*SBh + bseg,     g_ew1T + bn*288 + bseg);
    cpa16(s_bb + bn*SBh + bseg + 8, g_ew1T + bn*288 + bseg + 8);
    CP_COMMIT;

    // tail cols 256..287 + counts
    if (tid < TM) {
        int e = tid;
        const float* lp = g_lip + e2g[e0 + e]*9;
        #pragma unroll
        for (int u = 0; u < 9; u++) s_a[e*SAh + 256 + u] = __float2half(lp[u]);
        int ii = s_i[e], jj = s_j[e];
        #pragma unroll
        for (int c = 0; c < 3; c++) {
            float dd = frac[jj*3 + c] - frac[ii*3 + c];
            dd -= floorf(dd);
            s_a[e*SAh + 265 + c] = __float2half(dd);
        }
        #pragma unroll
        for (int u = 268; u < 288; u++) s_a[e*SAh + u] = __half(0.f);
        atomicAdd(&g_cnt[ii], 1);
    }

    float acc[4][4][4];
    #pragma unroll
    for (int mf = 0; mf < 4; mf++)
        #pragma unroll
        for (int nf = 0; nf < 4; nf++)
            #pragma unroll
            for (int u = 0; u < 4; u++) acc[mf][nf][u] = 0.f;

    CP_WAIT0;
    __syncthreads();

    // ---- GEMM1: K=288 (padded), 9 rounds of K=32 ----
    for (int ct = 0; ct < 9; ct++) {
        __half* dbuf = s_bb + ((ct+1)&1)*BHB;
        const __half* src; int rstr;
        if (ct < 8) { src = g_ew1T + (ct+1)*32; rstr = 288; }
        else        { src = g_ew2T;             rstr = 128; }
        cpa16(dbuf + bn*SBh + bseg,     src + (size_t)bn*rstr + bseg);
        cpa16(dbuf + bn*SBh + bseg + 8, src + (size_t)bn*rstr + bseg + 8);
        CP_COMMIT;
        const __half* bB = s_bb + (ct & 1)*BHB;
        #pragma unroll
        for (int kk = 0; kk < 32; kk += 16) {
            int kg = ct*32 + kk;
            uint32_t afr[4][4];
            #pragma unroll
            for (int mf = 0; mf < 4; mf++) LDA16(afr[mf], s_a, SAh, wm*64 + mf*16, kg);
            uint32_t bfr[4][2];
            #pragma unroll
            for (int nf = 0; nf < 4; nf++) LDB16K(bfr[nf], bB, SBh, wn*32 + nf*8, kk);
            #pragma unroll
            for (int mf = 0; mf < 4; mf++)
                #pragma unroll
                for (int nf = 0; nf < 4; nf++)
                    mma_f16(acc[mf][nf], afr[mf], bfr[nf]);
        }
        CP_WAIT0;
        __syncthreads();
    }

    // hidden = silu(acc + eb1) -> s_a cols 0..127
    #pragma unroll
    for (int mf = 0; mf < 4; mf++) {
        int r0 = wm*64 + mf*16 + (lane >> 2);
        #pragma unroll
        for (int nf = 0; nf < 4; nf++) {
            int n = wn*32 + nf*8 + (lane & 3)*2;
            float b0 = eb1[n], b1 = eb1[n + 1];
            *(__half2*)(s_a + r0*SAh + n) =
                __floats2half2_rn(silu_f(acc[mf][nf][0] + b0), silu_f(acc[mf][nf][1] + b1));
            *(__half2*)(s_a + (r0 + 8)*SAh + n) =
                __floats2half2_rn(silu_f(acc[mf][nf][2] + b0), silu_f(acc[mf][nf][3] + b1));
            #pragma unroll
            for (int u = 0; u < 4; u++) acc[mf][nf][u] = 0.f;
        }
    }
    __syncthreads();

    // ---- GEMM2: K=128, 4 rounds; chunk c in buf[(1+c)&1] ----
    for (int c = 0; c < 4; c++) {
        if (c < 3) {
            __half* dbuf = s_bb + (c & 1)*BHB;
            const __half* src = g_ew2T + (c+1)*32;
            cpa16(dbuf + bn*SBh + bseg,     src + bn*DD + bseg);
            cpa16(dbuf + bn*SBh + bseg + 8, src + bn*DD + bseg + 8);
            CP_COMMIT;
        }
        const __half* bB = s_bb + ((1 + c) & 1)*BHB;
        #pragma unroll
        for (int kk = 0; kk < 32; kk += 16) {
            int kg = c*32 + kk;
            uint32_t afr[4][4];
            #pragma unroll
            for (int mf = 0; mf < 4; mf++) LDA16(afr[mf], s_a, SAh, wm*64 + mf*16, kg);
            uint32_t bfr[4][2];
            #pragma unroll
            for (int nf = 0; nf < 4; nf++) LDB16K(bfr[nf], bB, SBh, wn*32 + nf*8, kk);
            #pragma unroll
            for (int mf = 0; mf < 4; mf++)
                #pragma unroll
                for (int nf = 0; nf < 4; nf++)
                    mma_f16(acc[mf][nf], afr[mf], bfr[nf]);
        }
        if (c < 3) { CP_WAIT0; }
        __syncthreads();
    }

    // epilogue: silu + bias, red.v2 scatter into g_agg (fp32)
    #pragma unroll
    for (int mf = 0; mf < 4; mf++) {
        #pragma unroll
        for (int rr = 0; rr < 2; rr++) {
            int m = wm*64 + mf*16 + (lane >> 2) + rr*8;
            float* ap = g_agg + (size_t)s_i[m]*DD;
            #pragma unroll
            for (int nf = 0; nf < 4; nf++) {
                int n = wn*32 + nf*8 + (lane & 3)*2;
                float v0 = silu_f(acc[mf][nf][rr*2 + 0] + eb2[n]);
                float v1 = silu_f(acc[mf][nf][rr*2 + 1] + eb2[n + 1]);
                asm volatile("red.global.add.v2.f32 [%0], {%1, %2};"
                             :: "l"(ap + n), "f"(v0), "f"(v1) : "memory");
            }
        }
    }
}

// ---------------- kernel 5: node MLP, fp16, K=32 rounds ----------------
#define TN 128
#define SAn 264    // conflict-free

__global__ __launch_bounds__(256, 2)
void node_kernel(const float* __restrict__ nfeat,
                 const float* __restrict__ nb1, const float* __restrict__ nb2,
                 float* __restrict__ out)
{
    extern __shared__ __half smh[];
    __half* s_a  = smh;               // TN*SAn (67584 B)
    __half* s_bb = smh + TN*SAn;      // 2*BHB  (20480 B)
    __shared__ float s_cnt[TN];

    int tid  = threadIdx.x, lane = tid & 31, wid = tid >> 5;
    int wm = wid >> 2, wn = wid & 3;
    int n0 = blockIdx.x * TN;
    int bn = tid >> 1, bseg = (tid & 1) * 16;

    if (tid < TN) {
        int n = min(n0 + tid, NN - 1);
        s_cnt[tid] = fmaxf((float)g_cnt[n], 1.f);
    }
    // h rows fp16 direct
    #pragma unroll
    for (int it = 0; it < 8; it++) {
        int idx = tid + it*256;
        int r = idx >> 4, seg = idx & 15;
        int n = min(n0 + r, NN - 1);
        cpa16(s_a + r*SAn + seg*8, g_h16 + (size_t)n*DD + seg*8);
    }
    cpa16(s_bb + bn*SBh + bseg,     g_nw1T + bn*256 + bseg);
    cpa16(s_bb + bn*SBh + bseg + 8, g_nw1T + bn*256 + bseg + 8);
    CP_COMMIT;
    __syncthreads();   // s_cnt visible

    // agg/cnt -> cols 128..255
    #pragma unroll
    for (int it = 0; it < 16; it++) {
        int idx = tid + it*256;
        int r = idx >> 5, c4 = (idx & 31) * 4;
        int n = min(n0 + r, NN - 1);
        float inv = __fdividef(1.f, s_cnt[r]);
        float4 v = *(const float4*)(g_agg + (size_t)n*DD + c4);
        __half* dst = s_a + r*SAn + DD + c4;
        *(__half2*)(dst)     = __floats2half2_rn(v.x * inv, v.y * inv);
        *(__half2*)(dst + 2) = __floats2half2_rn(v.z * inv, v.w * inv);
    }

    float acc[4][4][4];
    #pragma unroll
    for (int mf = 0; mf < 4; mf++)
        #pragma unroll
        for (int nf = 0; nf < 4; nf++)
            #pragma unroll
            for (int u = 0; u < 4; u++) acc[mf][nf][u] = 0.f;

    CP_WAIT0;
    __syncthreads();

    // ---- GEMM1: K=256, 8 rounds of K=32 ----
    for (int ct = 0; ct < 8; ct++) {
        __half* dbuf = s_bb + ((ct+1)&1)*BHB;
        const __half* src; int rstr;
        if (ct < 7) { src = g_nw1T + (ct+1)*32; rstr = 256; }
        else        { src = g_nw2T;             rstr = 128; }
        cpa16(dbuf + bn*SBh + bseg,     src + (size_t)bn*rstr + bseg);
        cpa16(dbuf + bn*SBh + bseg + 8, src + (size_t)bn*rstr + bseg + 8);
        CP_COMMIT;
        const __half* bB = s_bb + (ct & 1)*BHB;
        #pragma unroll
        for (int kk = 0; kk < 32; kk += 16) {
            int kg = ct*32 + kk;
            uint32_t afr[4][4];
            #pragma unroll
            for (int mf = 0; mf < 4; mf++) LDA16(afr[mf], s_a, SAn, wm*64 + mf*16, kg);
            uint32_t bfr[4][2];
            #pragma unroll
            for (int nf = 0; nf < 4; nf++) LDB16K(bfr[nf], bB, SBh, wn*32 + nf*8, kk);
            #pragma unroll
            for (int mf = 0; mf < 4; mf++)
                #pragma unroll
                for (int nf = 0; nf < 4; nf++)
                    mma_f16(acc[mf][nf], afr[mf], bfr[nf]);
        }
        CP_WAIT0;
        __syncthreads();
    }

    // hidden -> s_a cols 0..127
    #pragma unroll
    for (int mf = 0; mf < 4; mf++) {
        int r0 = wm*64 + mf*16 + (lane >> 2);
        #pragma unroll
        for (int nf = 0; nf < 4; nf++) {
            int n = wn*32 + nf*8 + (lane & 3)*2;
            float b0 = nb1[n], b1 = nb1[n + 1];
            *(__half2*)(s_a + r0*SAn + n) =
                __floats2half2_rn(silu_f(acc[mf][nf][0] + b0), silu_f(acc[mf][nf][1] + b1));
            *(__half2*)(s_a + (r0 + 8)*SAn + n) =
                __floats2half2_rn(silu_f(acc[mf][nf][2] + b0), silu_f(acc[mf][nf][3] + b1));
            #pragma unroll
            for (int u = 0; u < 4; u++) acc[mf][nf][u] = 0.f;
        }
    }
    __syncthreads();

    // ---- GEMM2: K=128, 4 rounds; chunk c in buf[c&1] ----
    for (int c = 0; c < 4; c++) {
        if (c < 3) {
            __half* dbuf = s_bb + ((c+1)&1)*BHB;
            const __half* src = g_nw2T + (c+1)*32;
            cpa16(dbuf + bn*SBh + bseg,     src + bn*DD + bseg);
            cpa16(dbuf + bn*SBh + bseg + 8, src + bn*DD + bseg + 8);
            CP_COMMIT;
        }
        const __half* bB = s_bb + (c & 1)*BHB;
        #pragma unroll
        for (int kk = 0; kk < 32; kk += 16) {
            int kg = c*32 + kk;
            uint32_t afr[4][4];
            #pragma unroll
            for (int mf = 0; mf < 4; mf++) LDA16(afr[mf], s_a, SAn, wm*64 + mf*16, kg);
            uint32_t bfr[4][2];
            #pragma unroll
            for (int nf = 0; nf < 4; nf++) LDB16K(bfr[nf], bB, SBh, wn*32 + nf*8, kk);
            #pragma unroll
            for (int mf = 0; mf < 4; mf++)
                #pragma unroll
                for (int nf = 0; nf < 4; nf++)
                    mma_f16(acc[mf][nf], afr[mf], bfr[nf]);
        }
        if (c < 3) { CP_WAIT0; }
        __syncthreads();
    }

    // epilogue: out = nfeat + silu(acc + nb2)
    #pragma unroll
    for (int mf = 0; mf < 4; mf++) {
        #pragma unroll
        for (int rr = 0; rr < 2; rr++) {
            int m = wm*64 + mf*16 + (lane >> 2) + rr*8;
            int n = n0 + m;
            if (n < NN) {
                const float* nfr = nfeat + (size_t)n*DD;
                float* orow = out + (size_t)n*DD;
                #pragma unroll
                for (int nf = 0; nf < 4; nf++) {
                    int col = wn*32 + nf*8 + (lane & 3)*2;
                    orow[col]     = nfr[col]     + silu_f(acc[mf][nf][rr*2 + 0] + nb2[col]);
                    orow[col + 1] = nfr[col + 1] + silu_f(acc[mf][nf][rr*2 + 1] + nb2[col + 1]);
                }
            }
        }
    }
}

// ---------------- launch ----------------
extern "C" void kernel_launch(void* const* d_in, const int* in_sizes, int n_in,
                              void* d_out, int out_size)
{
    const float* node_features = (const float*)d_in[0];
    const float* cond = (const float*)d_in[1];
    const int*   n2g  = (const int*)d_in[2];
    const float* frac = (const float*)d_in[3];
    const float* lat  = (const float*)d_in[4];
    const int*   edges= (const int*)d_in[5];
    const int*   e2g  = (const int*)d_in[6];
    const float* wq = (const float*)d_in[7];
    const float* bq = (const float*)d_in[8];
    const float* wk = (const float*)d_in[9];
    const float* bk = (const float*)d_in[10];
    const float* wv = (const float*)d_in[11];
    const float* bv = (const float*)d_in[12];
    const float* wo = (const float*)d_in[13];
    const float* bo = (const float*)d_in[14];
    const float* sw1= (const float*)d_in[15];
    const float* sb1= (const float*)d_in[16];
    const float* sw2= (const float*)d_in[17];
    const float* sb2= (const float*)d_in[18];
    const float* ew1= (const float*)d_in[19];
    const float* eb1= (const float*)d_in[20];
    const float* ew2= (const float*)d_in[21];
    const float* eb2= (const float*)d_in[22];
    const float* nw1= (const float*)d_in[23];
    const float* nb1= (const float*)d_in[24];
    const float* nw2= (const float*)d_in[25];
    const float* nb2= (const float*)d_in[26];
    float* out = (float*)d_out;

    const int attn_smem = 3*(AT*SQh*2) + 128*SBh*2 + 2*BHB*2
                        + 1024*4 + 128*4 + 8*4 + AT*40*2 + AT*8*4;   // ~94.8 KB
    const int edge_smem = (TM*SAh + 2*BHB) * 2;                      // 96,256 B
    const int node_smem = (TN*SAn + 2*BHB) * 2;                      // 88,064 B
    cudaFuncSetAttribute(attn_kernel, cudaFuncAttributeMaxDynamicSharedMemorySize, attn_smem);
    cudaFuncSetAttribute(edge_kernel, cudaFuncAttributeMaxDynamicSharedMemorySize, edge_smem);
    cudaFuncSetAttribute(node_kernel, cudaFuncAttributeMaxDynamicSharedMemorySize, node_smem);

    prep_kernel<<<BB*TT + BB, 128>>>(cond, wk, bk, wv, bv, lat);
    convw_kernel<<<544, 256>>>(ew1, ew2, nw1, nw2, wq, wo, sw1);
    zero_kernel<<<(NN*DD + 255) / 256, 256>>>();
    attn_kernel<<<(NN + AT - 1) / AT, 256, attn_smem>>>(node_features, frac, n2g,
                                                        bq, bo, sb1, sw2, sb2);
    edge_kernel<<<EE / TM, 256, edge_smem>>>(frac, edges, e2g, eb1, eb2);
    node_kernel<<<(NN + TN - 1) / TN, 256, node_smem>>>(node_features, nb1, nb2, out);
}

// round 11
// speedup vs baseline: 1.1202x; 1.0539x over previous
#include <cuda_runtime.h>
#include <cuda_fp16.h>
#include <math.h>
#include <stdint.h>

#define NN 50000
#define EE 800000
#define BB 256
#define DD 128
#define TT 8
#define KV_OFF (BB*TT*DD)

// ---------------- scratch (no allocations allowed) ----------------
__device__ __half g_h16[(size_t)NN*DD];     // post-attention node states (fp16)
__device__ float  g_KV[2*BB*TT*DD];         // Kc then Vc (fp32)
__device__ float  g_lip[BB*9];              // lattice inner products
__device__ float  g_agg[(size_t)NN*DD];     // scatter sums (fp32 atomics)
__device__ int    g_cnt[NN];                // scatter counts
// pre-converted, pre-transposed fp16 weights [N][K]
__device__ __half g_ew1T[DD*288];           // K padded 272->288
__device__ __half g_ew2T[DD*DD];
__device__ __half g_nw1T[DD*256];
__device__ __half g_nw2T[DD*DD];
__device__ __half g_wqT[DD*DD];
__device__ __half g_woT[DD*DD];
__device__ __half g_sw1T[DD*32];            // K padded 24->32
__device__ float  g_sw2T[8*DD];             // sw2 transposed [8][128] fp32

__device__ __forceinline__ float silu_f(float x) {
    return __fdividef(x, 1.f + __expf(-x));
}

// fp16 mma, fp32 accumulate
__device__ __forceinline__ void mma_f16(float* c, const uint32_t* a, const uint32_t* b) {
    asm volatile(
        "mma.sync.aligned.m16n8k16.row.col.f32.f16.f16.f32 "
        "{%0,%1,%2,%3}, {%4,%5,%6,%7}, {%8,%9}, {%0,%1,%2,%3};\n"
        : "+f"(c[0]), "+f"(c[1]), "+f"(c[2]), "+f"(c[3])
        : "r"(a[0]), "r"(a[1]), "r"(a[2]), "r"(a[3]), "r"(b[0]), "r"(b[1]));
}

__device__ __forceinline__ void cpa16(void* dst, const void* src) {
    uint32_t d = (uint32_t)__cvta_generic_to_shared(dst);
    asm volatile("cp.async.cg.shared.global [%0], [%1], 16;" :: "r"(d), "l"(src));
}
#define CP_COMMIT asm volatile("cp.async.commit_group;" ::: "memory")
#define CP_WAIT0  asm volatile("cp.async.wait_group 0;" ::: "memory")

// ldmatrix x4
__device__ __forceinline__ void ldsm4(uint32_t* r, const __half* p) {
    uint32_t a = (uint32_t)__cvta_generic_to_shared(p);
    asm volatile("ldmatrix.sync.aligned.m8n8.x4.shared.b16 {%0,%1,%2,%3}, [%4];"
        : "=r"(r[0]), "=r"(r[1]), "=r"(r[2]), "=r"(r[3]) : "r"(a));
}
// A fragment (m16 x k16): lanes 0-7 rows 0-7 k0 | 8-15 rows 8-15 k0 | 16-23 rows 0-7 k8 | 24-31 rows 8-15 k8
#define LDSMA(afr, base, SAx, rowbase, kg)                                        \
    ldsm4(afr, (base) + ((rowbase) + (lane & 15))*(SAx) + (kg) + ((lane >> 4) << 3))
// B double fragment (two adjacent nf, n8 x k16 each), B stored [n][k]:
// lanes 0-7 n0-7 k0 | 8-15 n0-7 k8 | 16-23 n8-15 k0 | 24-31 n8-15 k8
#define LDSMB2(b4, bB, SBx, ncol, kk)                                             \
    ldsm4(b4, (bB) + ((ncol) + (lane & 7) + ((lane >> 4) << 3))*(SBx) + (kk) + (((lane >> 3) & 1) << 3))

// B buffer geometry: 128 n-rows x (32 k + 8 pad) halfs
#define SBh 40
#define BHB (128*SBh)

// ---------------- kernel 1: K/V projection + lattice gram ----------------
__global__ void prep_kernel(const float* __restrict__ cond,
                            const float* __restrict__ wk, const float* __restrict__ bk,
                            const float* __restrict__ wv, const float* __restrict__ bv,
                            const float* __restrict__ lat)
{
    int b = blockIdx.x;
    if (b < BB*TT) {
        __shared__ float s_c[DD];
        int d = threadIdx.x;
        s_c[d] = cond[b*DD + d];
        __syncthreads();
        float ka = bk[d], va = bv[d];
        #pragma unroll 8
        for (int k = 0; k < DD; k++) {
            float c = s_c[k];
            ka = fmaf(c, wk[k*DD + d], ka);
            va = fmaf(c, wv[k*DD + d], va);
        }
        g_KV[b*DD + d] = ka;
        g_KV[KV_OFF + b*DD + d] = va;
    } else {
        int bb = b - BB*TT;
        int t = threadIdx.x;
        if (t < 9) {
            int i = t / 3, k2 = t % 3;
            const float* L = lat + bb*9;
            g_lip[bb*9 + t] = L[i*3+0]*L[k2*3+0] + L[i*3+1]*L[k2*3+1] + L[i*3+2]*L[k2*3+2];
        }
    }
}

// ---------------- kernel 1b: convert+transpose weights ----------------
// cumulative: ew1T 36864 | ew2T 53248 | nw1T 86016 | nw2T 102400
//             wqT 118784 | woT 135168 | sw1T 139264 | sw2T 140288
__global__ void convw_kernel(const float* __restrict__ ew1, const float* __restrict__ ew2,
                             const float* __restrict__ nw1, const float* __restrict__ nw2,
                             const float* __restrict__ wq,  const float* __restrict__ wo,
                             const float* __restrict__ sw1, const float* __restrict__ sw2)
{
    int idx = blockIdx.x * 256 + threadIdx.x;
    if (idx < 36864) {
        int n = idx / 288, k = idx % 288;
        g_ew1T[idx] = (k < 268) ? __float2half(ew1[k*DD + n]) : __half(0.f);
    } else if (idx < 53248) {
        int j = idx - 36864; int n = j / DD, k = j % DD;
        g_ew2T[j] = __float2half(ew2[k*DD + n]);
    } else if (idx < 86016) {
        int j = idx - 53248; int n = j / 256, k = j % 256;
        g_nw1T[j] = __float2half(nw1[k*DD + n]);
    } else if (idx < 102400) {
        int j = idx - 86016; int n = j / DD, k = j % DD;
        g_nw2T[j] = __float2half(nw2[k*DD + n]);
    } else if (idx < 118784) {
        int j = idx - 102400; int n = j / DD, k = j % DD;
        g_wqT[j] = __float2half(wq[k*DD + n]);
    } else if (idx < 135168) {
        int j = idx - 118784; int n = j / DD, k = j % DD;
        g_woT[j] = __float2half(wo[k*DD + n]);
    } else if (idx < 139264) {
        int j = idx - 135168; int n = j / 32, k = j % 32;
        g_sw1T[j] = (k < 24) ? __float2half(sw1[k*DD + n]) : __half(0.f);
    } else if (idx < 140288) {
        int j = idx - 139264; int t = j / DD, k = j % DD;
        g_sw2T[j] = sw2[k*8 + t];
    }
}

// ---------------- kernel 2: zero scatter buffers ----------------
__global__ void zero_kernel()
{
    int idx = blockIdx.x * blockDim.x + threadIdx.x;
    if (idx < NN*DD) g_agg[idx] = 0.f;
    if (idx < NN)    g_cnt[idx] = 0;
}

// ---------------- kernel 3: cross-attention, fp16 mma + ldmatrix ----------------
// Tile 64 nodes, 8 warps (2 wm x 4 wn), warp tile 32x32 (mf=2, nf=4).
#define AT 64
#define SQh 136    // h/q/ca tile stride (halfs)
#define SW2S 132   // s_sw2T row stride (floats)

__global__ __launch_bounds__(256, 2)
void attn_kernel(const float* __restrict__ nfeat, const float* __restrict__ frac,
                 const int* __restrict__ n2g,
                 const float* __restrict__ bq, const float* __restrict__ bo,
                 const float* __restrict__ sb1, const float* __restrict__ sb2)
{
    extern __shared__ char smraw[];
    __half* s_h   = (__half*)smraw;                 // 64*136
    __half* s_hid = s_h + AT*SQh;                   // 64*136
    __half* s_q   = s_hid + AT*SQh;                 // 64*136
    __half* s_bsw = s_q + AT*SQh;                   // 128*40
    __half* s_bb  = s_bsw + 128*SBh;                // 2*BHB
    __half* s_enc = s_bb + 2*BHB;                   // 64*40
    float*  s_sw2T = (float*)(s_enc + AT*40);       // 8*132
    float*  s_sb1 = s_sw2T + 8*SW2S;                // 128
    float*  s_sb2 = s_sb1 + 128;                    // 8
    float*  s_att = s_sb2 + 8;                      // 64*8
    __shared__ int s_g[AT];

    int tid = threadIdx.x, lane = tid & 31, wid = tid >> 5;
    int wm = wid >> 2, wn = wid & 3;
    int n0 = blockIdx.x * AT;
    int bn = tid >> 1, bseg = (tid & 1) * 16;

    if (tid < AT) s_g[tid] = n2g[min(n0 + tid, NN - 1)];

    // async: sw1T tile, sw2T, sb1, sb2, wqT chunk0
    cpa16(s_bsw + bn*SBh + bseg,     g_sw1T + bn*32 + bseg);
    cpa16(s_bsw + bn*SBh + bseg + 8, g_sw1T + bn*32 + bseg + 8);
    {
        int row = tid >> 5, chunk = tid & 31;
        cpa16(s_sw2T + row*SW2S + chunk*4, g_sw2T + row*DD + chunk*4);
    }
    if (tid < 32) cpa16(s_sb1 + tid*4, sb1 + tid*4);
    if (tid < 2)  cpa16(s_sb2 + tid*4, sb2 + tid*4);
    cpa16(s_bb + bn*SBh + bseg,     g_wqT + bn*DD + bseg);
    cpa16(s_bb + bn*SBh + bseg + 8, g_wqT + bn*DD + bseg + 8);
    CP_COMMIT;

    // h tile: fp32 load + fp16 convert
    #pragma unroll
    for (int it = 0; it < 8; it++) {
        int idx = tid + it*256;
        int r = idx >> 5, c4 = (idx & 31) * 4;
        int n = min(n0 + r, NN - 1);
        float4 v = *(const float4*)(nfeat + (size_t)n*DD + c4);
        __half* dst = s_h + r*SQh + c4;
        *(__half2*)(dst)     = __floats2half2_rn(v.x, v.y);
        *(__half2*)(dst + 2) = __floats2half2_rn(v.z, v.w);
    }
    // enc
    {
        int n = tid >> 2, sub = tid & 3;
        int nn = min(n0 + n, NN - 1);
        float f0 = frac[nn*3+0], f1 = frac[nn*3+1], f2 = frac[nn*3+2];
        #pragma unroll
        for (int k = sub; k < 24; k += 4) {
            int ii = k % 12, c = ii >> 2, j = ii & 3;
            float fv = (c == 0) ? f0 : ((c == 1) ? f1 : f2);
            float ph = fv * ((float)(1 << j) * 3.14159265358979323846f);
            s_enc[n*40 + k] = __float2half((k < 12) ? sinf(ph) : cosf(ph));
        }
        s_enc[n*40 + 24 + sub] = __half(0.f);
        s_enc[n*40 + 28 + sub] = __half(0.f);
    }
    CP_WAIT0;
    __syncthreads();

    float acc[2][4][4];
    #pragma unroll
    for (int mf = 0; mf < 2; mf++)
        #pragma unroll
        for (int nf = 0; nf < 4; nf++)
            #pragma unroll
            for (int u = 0; u < 4; u++) acc[mf][nf][u] = 0.f;

    // ---- bias GEMM: hidden = silu(enc @ sw1 + sb1), one K=32 round ----
    #pragma unroll
    for (int kk = 0; kk < 32; kk += 16) {
        uint32_t afr[2][4];
        #pragma unroll
        for (int mf = 0; mf < 2; mf++) LDSMA(afr[mf], s_enc, 40, wm*32 + mf*16, kk);
        uint32_t bfr[4][2];
        LDSMB2(bfr[0], s_bsw, SBh, wn*32, kk);
        LDSMB2(bfr[2], s_bsw, SBh, wn*32 + 16, kk);
        #pragma unroll
        for (int mf = 0; mf < 2; mf++)
            #pragma unroll
            for (int nf = 0; nf < 4; nf++)
                mma_f16(acc[mf][nf], afr[mf], bfr[nf]);
    }
    #pragma unroll
    for (int mf = 0; mf < 2; mf++) {
        int r0 = wm*32 + mf*16 + (lane >> 2);
        #pragma unroll
        for (int nf = 0; nf < 4; nf++) {
            int n = wn*32 + nf*8 + (lane & 3)*2;
            float b0 = s_sb1[n], b1 = s_sb1[n + 1];
            *(__half2*)(s_hid + r0*SQh + n) =
                __floats2half2_rn(silu_f(acc[mf][nf][0] + b0), silu_f(acc[mf][nf][1] + b1));
            *(__half2*)(s_hid + (r0 + 8)*SQh + n) =
                __floats2half2_rn(silu_f(acc[mf][nf][2] + b0), silu_f(acc[mf][nf][3] + b1));
            #pragma unroll
            for (int u = 0; u < 4; u++) acc[mf][nf][u] = 0.f;
        }
    }

    // ---- GEMM Q = h @ wq: 4 rounds of K=32 ----
    for (int ct = 0; ct < 4; ct++) {
        __half* dbuf = s_bb + ((ct+1)&1)*BHB;
        const __half* src = (ct < 3) ? (g_wqT + (ct+1)*32) : g_woT;
        cpa16(dbuf + bn*SBh + bseg,     src + bn*DD + bseg);
        cpa16(dbuf + bn*SBh + bseg + 8, src + bn*DD + bseg + 8);
        CP_COMMIT;
        const __half* bB = s_bb + (ct & 1)*BHB;
        #pragma unroll
        for (int kk = 0; kk < 32; kk += 16) {
            int kg = ct*32 + kk;
            uint32_t afr[2][4];
            #pragma unroll
            for (int mf = 0; mf < 2; mf++) LDSMA(afr[mf], s_h, SQh, wm*32 + mf*16, kg);
            uint32_t bfr[4][2];
            LDSMB2(bfr[0], bB, SBh, wn*32, kk);
            LDSMB2(bfr[2], bB, SBh, wn*32 + 16, kk);
            #pragma unroll
            for (int mf = 0; mf < 2; mf++)
                #pragma unroll
                for (int nf = 0; nf < 4; nf++)
                    mma_f16(acc[mf][nf], afr[mf], bfr[nf]);
        }
        CP_WAIT0;
        __syncthreads();
    }
    #pragma unroll
    for (int mf = 0; mf < 2; mf++) {
        int r0 = wm*32 + mf*16 + (lane >> 2);
        #pragma unroll
        for (int nf = 0; nf < 4; nf++) {
            int n = wn*32 + nf*8 + (lane & 3)*2;
            float b0 = bq[n], b1 = bq[n + 1];
            *(__half2*)(s_q + r0*SQh + n) =
                __floats2half2_rn(acc[mf][nf][0] + b0, acc[mf][nf][1] + b1);
            *(__half2*)(s_q + (r0 + 8)*SQh + n) =
                __floats2half2_rn(acc[mf][nf][2] + b0, acc[mf][nf][3] + b1);
            #pragma unroll
            for (int u = 0; u < 4; u++) acc[mf][nf][u] = 0.f;
        }
    }
    __syncthreads();

    // ---- scores + spatial bias + softmax: thread = (node, sub of 4), vectorized ----
    {
        int n = tid >> 2, sub = tid & 3;
        int gg = s_g[n];
        int t0 = sub*2, t1 = t0 + 1;
        const float4* K0 = (const float4*)(g_KV + (size_t)(gg*TT + t0)*DD);
        const float4* K1 = (const float4*)(g_KV + (size_t)(gg*TT + t1)*DD);
        const __half2* qq = (const __half2*)(s_q + n*SQh);
        const __half2* hh = (const __half2*)(s_hid + n*SQh);
        const float4* w0 = (const float4*)(s_sw2T + t0*SW2S);
        const float4* w1 = (const float4*)(s_sw2T + t1*SW2S);
        float sc0 = 0.f, sc1 = 0.f, bi0 = 0.f, bi1 = 0.f;
        #pragma unroll 4
        for (int k4 = 0; k4 < 32; k4++) {
            float4 a = K0[k4], b = K1[k4], wa = w0[k4], wb = w1[k4];
            float2 q0 = __half22float2(qq[2*k4]), q1 = __half22float2(qq[2*k4 + 1]);
            float2 h0 = __half22float2(hh[2*k4]), h1 = __half22float2(hh[2*k4 + 1]);
            sc0 = fmaf(q0.x, a.x, sc0); sc0 = fmaf(q0.y, a.y, sc0);
            sc0 = fmaf(q1.x, a.z, sc0); sc0 = fmaf(q1.y, a.w, sc0);
            sc1 = fmaf(q0.x, b.x, sc1); sc1 = fmaf(q0.y, b.y, sc1);
            sc1 = fmaf(q1.x, b.z, sc1); sc1 = fmaf(q1.y, b.w, sc1);
            bi0 = fmaf(h0.x, wa.x, bi0); bi0 = fmaf(h0.y, wa.y, bi0);
            bi0 = fmaf(h1.x, wa.z, bi0); bi0 = fmaf(h1.y, wa.w, bi0);
            bi1 = fmaf(h0.x, wb.x, bi1); bi1 = fmaf(h0.y, wb.y, bi1);
            bi1 = fmaf(h1.x, wb.z, bi1); bi1 = fmaf(h1.y, wb.w, bi1);
        }
        float v0 = sc0 * 0.08838834764831845f + bi0 + s_sb2[t0];
        float v1 = sc1 * 0.08838834764831845f + bi1 + s_sb2[t1];
        float m = fmaxf(v0, v1);
        m = fmaxf(m, __shfl_xor_sync(0xffffffffu, m, 1, 4));
        m = fmaxf(m, __shfl_xor_sync(0xffffffffu, m, 2, 4));
        float e0 = __expf(v0 - m), e1 = __expf(v1 - m);
        float s = e0 + e1;
        s += __shfl_xor_sync(0xffffffffu, s, 1, 4);
        s += __shfl_xor_sync(0xffffffffu, s, 2, 4);
        float inv = __fdividef(1.f, s);
        s_att[n*8 + t0] = e0 * inv;
        s_att[n*8 + t1] = e1 * inv;
    }
    __syncthreads();

    // ---- ca = attn @ V -> s_q (fp16) ----
    #pragma unroll
    for (int it = 0; it < 16; it++) {
        int idx = tid + it*256;
        int n = idx >> 6, c = (idx & 63) * 2;
        const float* Vr = g_KV + KV_OFF + (size_t)s_g[n]*TT*DD + c;
        const float* at = s_att + n*8;
        float a0 = 0.f, a1 = 0.f;
        #pragma unroll
        for (int t = 0; t < 8; t++) {
            a0 = fmaf(at[t], Vr[t*DD],     a0);
            a1 = fmaf(at[t], Vr[t*DD + 1], a1);
        }
        *(__half2*)(s_q + n*SQh + c) = __floats2half2_rn(a0, a1);
    }
    __syncthreads();

    // ---- GEMM out = ca @ wo: 4 rounds (chunk0 already in buf0) ----
    for (int c = 0; c < 4; c++) {
        if (c < 3) {
            __half* dbuf = s_bb + ((c+1)&1)*BHB;
            const __half* src = g_woT + (c+1)*32;
            cpa16(dbuf + bn*SBh + bseg,     src + bn*DD + bseg);
            cpa16(dbuf + bn*SBh + bseg + 8, src + bn*DD + bseg + 8);
            CP_COMMIT;
        }
        const __half* bB = s_bb + (c & 1)*BHB;
        #pragma unroll
        for (int kk = 0; kk < 32; kk += 16) {
            int kg = c*32 + kk;
            uint32_t afr[2][4];
            #pragma unroll
            for (int mf = 0; mf < 2; mf++) LDSMA(afr[mf], s_q, SQh, wm*32 + mf*16, kg);
            uint32_t bfr[4][2];
            LDSMB2(bfr[0], bB, SBh, wn*32, kk);
            LDSMB2(bfr[2], bB, SBh, wn*32 + 16, kk);
            #pragma unroll
            for (int mf = 0; mf < 2; mf++)
                #pragma unroll
                for (int nf = 0; nf < 4; nf++)
                    mma_f16(acc[mf][nf], afr[mf], bfr[nf]);
        }
        if (c < 3) { CP_WAIT0; }
        __syncthreads();
    }

    // epilogue: g_h16 = half(h + ca@wo + bo)
    #pragma unroll
    for (int mf = 0; mf < 2; mf++) {
        #pragma unroll
        for (int rr = 0; rr < 2; rr++) {
            int m = wm*32 + mf*16 + (lane >> 2) + rr*8;
            int n = n0 + m;
            if (n < NN) {
                __half* orow = g_h16 + (size_t)n*DD;
                const __half* hrow = s_h + m*SQh;
                #pragma unroll
                for (int nf = 0; nf < 4; nf++) {
                    int col = wn*32 + nf*8 + (lane & 3)*2;
                    float v0 = __half2float(hrow[col])     + acc[mf][nf][rr*2 + 0] + bo[col];
                    float v1 = __half2float(hrow[col + 1]) + acc[mf][nf][rr*2 + 1] + bo[col + 1];
                    *(__half2*)(orow + col) = __floats2half2_rn(v0, v1);
                }
            }
        }
    }
}

// ---------------- kernel 4: edge MLP, fp16 + ldmatrix ----------------
#define TM 128
#define SAh 296

__global__ __launch_bounds__(256, 2)
void edge_kernel(const float* __restrict__ frac,
                 const int* __restrict__ edges, const int* __restrict__ e2g,
                 const float* __restrict__ eb1, const float* __restrict__ eb2)
{
    extern __shared__ __half smh[];
    __half* s_a  = smh;               // TM*SAh
    __half* s_bb = smh + TM*SAh;      // 2*BHB
    __shared__ int s_i[TM], s_j[TM];

    int tid  = threadIdx.x, lane = tid & 31, wid = tid >> 5;
    int wm = wid >> 2, wn = wid & 3;
    int e0 = blockIdx.x * TM;
    int bn = tid >> 1, bseg = (tid & 1) * 16;

    if (tid < TM) {
        s_i[tid] = edges[e0 + tid];
        s_j[tid] = edges[EE + e0 + tid];
    }
    __syncthreads();

    #pragma unroll
    for (int it = 0; it < 16; it++) {
        int idx = tid + it*256;
        int r = idx >> 4, seg = idx & 15;
        int e = r >> 1, p = r & 1;
        int node = p ? s_j[e] : s_i[e];
        cpa16(s_a + e*SAh + p*DD + seg*8, g_h16 + (size_t)node*DD + seg*8);
    }
    cpa16(s_bb + bn*SBh + bseg,     g_ew1T + bn*288 + bseg);
    cpa16(s_bb + bn*SBh + bseg + 8, g_ew1T + bn*288 + bseg + 8);
    CP_COMMIT;

    if (tid < TM) {
        int e = tid;
        const float* lp = g_lip + e2g[e0 + e]*9;
        #pragma unroll
        for (int u = 0; u < 9; u++) s_a[e*SAh + 256 + u] = __float2half(lp[u]);
        int ii = s_i[e], jj = s_j[e];
        #pragma unroll
        for (int c = 0; c < 3; c++) {
            float dd = frac[jj*3 + c] - frac[ii*3 + c];
            dd -= floorf(dd);
            s_a[e*SAh + 265 + c] = __float2half(dd);
        }
        #pragma unroll
        for (int u = 268; u < 288; u++) s_a[e*SAh + u] = __half(0.f);
        atomicAdd(&g_cnt[ii], 1);
    }

    float acc[4][4][4];
    #pragma unroll
    for (int mf = 0; mf < 4; mf++)
        #pragma unroll
        for (int nf = 0; nf < 4; nf++)
            #pragma unroll
            for (int u = 0; u < 4; u++) acc[mf][nf][u] = 0.f;

    CP_WAIT0;
    __syncthreads();

    // ---- GEMM1: K=288, 9 rounds of K=32 ----
    for (int ct = 0; ct < 9; ct++) {
        __half* dbuf = s_bb + ((ct+1)&1)*BHB;
        const __half* src; int rstr;
        if (ct < 8) { src = g_ew1T + (ct+1)*32; rstr = 288; }
        else        { src = g_ew2T;             rstr = 128; }
        cpa16(dbuf + bn*SBh + bseg,     src + (size_t)bn*rstr + bseg);
        cpa16(dbuf + bn*SBh + bseg + 8, src + (size_t)bn*rstr + bseg + 8);
        CP_COMMIT;
        const __half* bB = s_bb + (ct & 1)*BHB;
        #pragma unroll
        for (int kk = 0; kk < 32; kk += 16) {
            int kg = ct*32 + kk;
            uint32_t afr[4][4];
            #pragma unroll
            for (int mf = 0; mf < 4; mf++) LDSMA(afr[mf], s_a, SAh, wm*64 + mf*16, kg);
            uint32_t bfr[4][2];
            LDSMB2(bfr[0], bB, SBh, wn*32, kk);
            LDSMB2(bfr[2], bB, SBh, wn*32 + 16, kk);
            #pragma unroll
            for (int mf = 0; mf < 4; mf++)
                #pragma unroll
                for (int nf = 0; nf < 4; nf++)
                    mma_f16(acc[mf][nf], afr[mf], bfr[nf]);
        }
        CP_WAIT0;
        __syncthreads();
    }

    // hidden = silu(acc + eb1) -> s_a cols 0..127
    #pragma unroll
    for (int mf = 0; mf < 4; mf++) {
        int r0 = wm*64 + mf*16 + (lane >> 2);
        #pragma unroll
        for (int nf = 0; nf < 4; nf++) {
            int n = wn*32 + nf*8 + (lane & 3)*2;
            float b0 = eb1[n], b1 = eb1[n + 1];
            *(__half2*)(s_a + r0*SAh + n) =
                __floats2half2_rn(silu_f(acc[mf][nf][0] + b0), silu_f(acc[mf][nf][1] + b1));
            *(__half2*)(s_a + (r0 + 8)*SAh + n) =
                __floats2half2_rn(silu_f(acc[mf][nf][2] + b0), silu_f(acc[mf][nf][3] + b1));
            #pragma unroll
            for (int u = 0; u < 4; u++) acc[mf][nf][u] = 0.f;
        }
    }
    __syncthreads();

    // ---- GEMM2: K=128, 4 rounds; chunk c in buf[(1+c)&1] ----
    for (int c = 0; c < 4; c++) {
        if (c < 3) {
            __half* dbuf = s_bb + (c & 1)*BHB;
            const __half* src = g_ew2T + (c+1)*32;
            cpa16(dbuf + bn*SBh + bseg,     src + bn*DD + bseg);
            cpa16(dbuf + bn*SBh + bseg + 8, src + bn*DD + bseg + 8);
            CP_COMMIT;
        }
        const __half* bB = s_bb + ((1 + c) & 1)*BHB;
        #pragma unroll
        for (int kk = 0; kk < 32; kk += 16) {
            int kg = c*32 + kk;
            uint32_t afr[4][4];
            #pragma unroll
            for (int mf = 0; mf < 4; mf++) LDSMA(afr[mf], s_a, SAh, wm*64 + mf*16, kg);
            uint32_t bfr[4][2];
            LDSMB2(bfr[0], bB, SBh, wn*32, kk);
            LDSMB2(bfr[2], bB, SBh, wn*32 + 16, kk);
            #pragma unroll
            for (int mf = 0; mf < 4; mf++)
                #pragma unroll
                for (int nf = 0; nf < 4; nf++)
                    mma_f16(acc[mf][nf], afr[mf], bfr[nf]);
        }
        if (c < 3) { CP_WAIT0; }
        __syncthreads();
    }

    // epilogue: silu + bias, red.v2 scatter into g_agg (fp32)
    #pragma unroll
    for (int mf = 0; mf < 4; mf++) {
        #pragma unroll
        for (int rr = 0; rr < 2; rr++) {
            int m = wm*64 + mf*16 + (lane >> 2) + rr*8;
            float* ap = g_agg + (size_t)s_i[m]*DD;
            #pragma unroll
            for (int nf = 0; nf < 4; nf++) {
                int n = wn*32 + nf*8 + (lane & 3)*2;
                float v0 = silu_f(acc[mf][nf][rr*2 + 0] + eb2[n]);
                float v1 = silu_f(acc[mf][nf][rr*2 + 1] + eb2[n + 1]);
                asm volatile("red.global.add.v2.f32 [%0], {%1, %2};"
                             :: "l"(ap + n), "f"(v0), "f"(v1) : "memory");
            }
        }
    }
}

// ---------------- kernel 5: node MLP, fp16 + ldmatrix ----------------
#define TN 128
#define SAn 264

__global__ __launch_bounds__(256, 2)
void node_kernel(const float* __restrict__ nfeat,
                 const float* __restrict__ nb1, const float* __restrict__ nb2,
                 float* __restrict__ out)
{
    extern __shared__ __half smh[];
    __half* s_a  = smh;               // TN*SAn
    __half* s_bb = smh + TN*SAn;      // 2*BHB
    __shared__ float s_cnt[TN];

    int tid  = threadIdx.x, lane = tid & 31, wid = tid >> 5;
    int wm = wid >> 2, wn = wid & 3;
    int n0 = blockIdx.x * TN;
    int bn = tid >> 1, bseg = (tid & 1) * 16;

    if (tid < TN) {
        int n = min(n0 + tid, NN - 1);
        s_cnt[tid] = fmaxf((float)g_cnt[n], 1.f);
    }
    #pragma unroll
    for (int it = 0; it < 8; it++) {
        int idx = tid + it*256;
        int r = idx >> 4, seg = idx & 15;
        int n = min(n0 + r, NN - 1);
        cpa16(s_a + r*SAn + seg*8, g_h16 + (size_t)n*DD + seg*8);
    }
    cpa16(s_bb + bn*SBh + bseg,     g_nw1T + bn*256 + bseg);
    cpa16(s_bb + bn*SBh + bseg + 8, g_nw1T + bn*256 + bseg + 8);
    CP_COMMIT;
    __syncthreads();

    #pragma unroll
    for (int it = 0; it < 16; it++) {
        int idx = tid + it*256;
        int r = idx >> 5, c4 = (idx & 31) * 4;
        int n = min(n0 + r, NN - 1);
        float inv = __fdividef(1.f, s_cnt[r]);
        float4 v = *(const float4*)(g_agg + (size_t)n*DD + c4);
        __half* dst = s_a + r*SAn + DD + c4;
        *(__half2*)(dst)     = __floats2half2_rn(v.x * inv, v.y * inv);
        *(__half2*)(dst + 2) = __floats2half2_rn(v.z * inv, v.w * inv);
    }

    float acc[4][4][4];
    #pragma unroll
    for (int mf = 0; mf < 4; mf++)
        #pragma unroll
        for (int nf = 0; nf < 4; nf++)
            #pragma unroll
            for (int u = 0; u < 4; u++) acc[mf][nf][u] = 0.f;

    CP_WAIT0;
    __syncthreads();

    // ---- GEMM1: K=256, 8 rounds of K=32 ----
    for (int ct = 0; ct < 8; ct++) {
        __half* dbuf = s_bb + ((ct+1)&1)*BHB;
        const __half* src; int rstr;
        if (ct < 7) { src = g_nw1T + (ct+1)*32; rstr = 256; }
        else        { src = g_nw2T;             rstr = 128; }
        cpa16(dbuf + bn*SBh + bseg,     src + (size_t)bn*rstr + bseg);
        cpa16(dbuf + bn*SBh + bseg + 8, src + (size_t)bn*rstr + bseg + 8);
        CP_COMMIT;
        const __half* bB = s_bb + (ct & 1)*BHB;
        #pragma unroll
        for (int kk = 0; kk < 32; kk += 16) {
            int kg = ct*32 + kk;
            uint32_t afr[4][4];
            #pragma unroll
            for (int mf = 0; mf < 4; mf++) LDSMA(afr[mf], s_a, SAn, wm*64 + mf*16, kg);
            uint32_t bfr[4][2];
            LDSMB2(bfr[0], bB, SBh, wn*32, kk);
            LDSMB2(bfr[2], bB, SBh, wn*32 + 16, kk);
            #pragma unroll
            for (int mf = 0; mf < 4; mf++)
                #pragma unroll
                for (int nf = 0; nf < 4; nf++)
                    mma_f16(acc[mf][nf], afr[mf], bfr[nf]);
        }
        CP_WAIT0;
        __syncthreads();
    }

    // hidden -> s_a cols 0..127
    #pragma unroll
    for (int mf = 0; mf < 4; mf++) {
        int r0 = wm*64 + mf*16 + (lane >> 2);
        #pragma unroll
        for (int nf = 0; nf < 4; nf++) {
            int n = wn*32 + nf*8 + (lane & 3)*2;
            float b0 = nb1[n], b1 = nb1[n + 1];
            *(__half2*)(s_a + r0*SAn + n) =
                __floats2half2_rn(silu_f(acc[mf][nf][0] + b0), silu_f(acc[mf][nf][1] + b1));
            *(__half2*)(s_a + (r0 + 8)*SAn + n) =
                __floats2half2_rn(silu_f(acc[mf][nf][2] + b0), silu_f(acc[mf][nf][3] + b1));
            #pragma unroll
            for (int u = 0; u < 4; u++) acc[mf][nf][u] = 0.f;
        }
    }
    __syncthreads();

    // ---- GEMM2: K=128, 4 rounds; chunk c in buf[c&1] ----
    for (int c = 0; c < 4; c++) {
        if (c < 3) {
            __half* dbuf = s_bb + ((c+1)&1)*BHB;
            const __half* src = g_nw2T + (c+1)*32;
            cpa16(dbuf + bn*SBh + bseg,     src + bn*DD + bseg);
            cpa16(dbuf + bn*SBh + bseg + 8, src + bn*DD + bseg + 8);
            CP_COMMIT;
        }
        const __half* bB = s_bb + (c & 1)*BHB;
        #pragma unroll
        for (int kk = 0; kk < 32; kk += 16) {
            int kg = c*32 + kk;
            uint32_t afr[4][4];
            #pragma unroll
            for (int mf = 0; mf < 4; mf++) LDSMA(afr[mf], s_a, SAn, wm*64 + mf*16, kg);
            uint32_t bfr[4][2];
            LDSMB2(bfr[0], bB, SBh, wn*32, kk);
            LDSMB2(bfr[2], bB, SBh, wn*32 + 16, kk);
            #pragma unroll
            for (int mf = 0; mf < 4; mf++)
                #pragma unroll
                for (int nf = 0; nf < 4; nf++)
                    mma_f16(acc[mf][nf], afr[mf], bfr[nf]);
        }
        if (c < 3) { CP_WAIT0; }
        __syncthreads();
    }

    // epilogue: out = nfeat + silu(acc + nb2)
    #pragma unroll
    for (int mf = 0; mf < 4; mf++) {
        #pragma unroll
        for (int rr = 0; rr < 2; rr++) {
            int m = wm*64 + mf*16 + (lane >> 2) + rr*8;
            int n = n0 + m;
            if (n < NN) {
                const float* nfr = nfeat + (size_t)n*DD;
                float* orow = out + (size_t)n*DD;
                #pragma unroll
                for (int nf = 0; nf < 4; nf++) {
                    int col = wn*32 + nf*8 + (lane & 3)*2;
                    orow[col]     = nfr[col]     + silu_f(acc[mf][nf][rr*2 + 0] + nb2[col]);
                    orow[col + 1] = nfr[col + 1] + silu_f(acc[mf][nf][rr*2 + 1] + nb2[col + 1]);
                }
            }
        }
    }
}

// ---------------- launch ----------------
extern "C" void kernel_launch(void* const* d_in, const int* in_sizes, int n_in,
                              void* d_out, int out_size)
{
    const float* node_features = (const float*)d_in[0];
    const float* cond = (const float*)d_in[1];
    const int*   n2g  = (const int*)d_in[2];
    const float* frac = (const float*)d_in[3];
    const float* lat  = (const float*)d_in[4];
    const int*   edges= (const int*)d_in[5];
    const int*   e2g  = (const int*)d_in[6];
    const float* wq = (const float*)d_in[7];
    const float* bq = (const float*)d_in[8];
    const float* wk = (const float*)d_in[9];
    const float* bk = (const float*)d_in[10];
    const float* wv = (const float*)d_in[11];
    const float* bv = (const float*)d_in[12];
    const float* wo = (const float*)d_in[13];
    const float* bo = (const float*)d_in[14];
    const float* sw1= (const float*)d_in[15];
    const float* sb1= (const float*)d_in[16];
    const float* sw2= (const float*)d_in[17];
    const float* sb2= (const float*)d_in[18];
    const float* ew1= (const float*)d_in[19];
    const float* eb1= (const float*)d_in[20];
    const float* ew2= (const float*)d_in[21];
    const float* eb2= (const float*)d_in[22];
    const float* nw1= (const float*)d_in[23];
    const float* nb1= (const float*)d_in[24];
    const float* nw2= (const float*)d_in[25];
    const float* nb2= (const float*)d_in[26];
    float* out = (float*)d_out;

    const int attn_smem = (3*AT*SQh + 128*SBh + 2*BHB + AT*40) * 2
                        + (8*SW2S + 128 + 8 + AT*8) * 4;             // 94,880 B
    const int edge_smem = (TM*SAh + 2*BHB) * 2;                      // 96,256 B
    const int node_smem = (TN*SAn + 2*BHB) * 2;                      // 88,064 B
    cudaFuncSetAttribute(attn_kernel, cudaFuncAttributeMaxDynamicSharedMemorySize, attn_smem);
    cudaFuncSetAttribute(edge_kernel, cudaFuncAttributeMaxDynamicSharedMemorySize, edge_smem);
    cudaFuncSetAttribute(node_kernel, cudaFuncAttributeMaxDynamicSharedMemorySize, node_smem);

    prep_kernel<<<BB*TT + BB, 128>>>(cond, wk, bk, wv, bv, lat);
    convw_kernel<<<549, 256>>>(ew1, ew2, nw1, nw2, wq, wo, sw1, sw2);
    zero_kernel<<<(NN*DD + 255) / 256, 256>>>();
    attn_kernel<<<(NN + AT - 1) / AT, 256, attn_smem>>>(node_features, frac, n2g,
                                                        bq, bo, sb1, sb2);
    edge_kernel<<<EE / TM, 256, edge_smem>>>(frac, edges, e2g, eb1, eb2);
    node_kernel<<<(NN + TN - 1) / TN, 256, node_smem>>>(node_features, nb1, nb2, out);
}

// round 12
// speedup vs baseline: 1.1746x; 1.0486x over previous
#include <cuda_runtime.h>
#include <cuda_fp16.h>
#include <math.h>
#include <stdint.h>

#define NN 50000
#define EE 800000
#define BB 256
#define DD 128
#define TT 8
#define KV_OFF (BB*TT*DD)

// ---------------- scratch (no allocations allowed) ----------------
__device__ __half g_h16[(size_t)NN*DD];     // post-attention node states (fp16)
__device__ __half g_KV16[2*BB*TT*DD];       // Kc then Vc (fp16)
__device__ float  g_lip[BB*9];              // lattice inner products
__device__ float  g_agg[(size_t)NN*DD];     // scatter sums (fp32 atomics)
__device__ int    g_cnt[NN];                // scatter counts
// pre-converted, pre-transposed fp16 weights [N][K]
__device__ __half g_ew1T[DD*288];           // K padded 272->288
__device__ __half g_ew2T[DD*DD];
__device__ __half g_nw1T[DD*256];
__device__ __half g_nw2T[DD*DD];
__device__ __half g_wqT[DD*DD];
__device__ __half g_woT[DD*DD];
__device__ __half g_sw1T[DD*32];            // K padded 24->32
__device__ __half g_sw2h[8*DD];             // sw2 transposed [8][128] fp16

__device__ __forceinline__ float silu_f(float x) {
    return __fdividef(x, 1.f + __expf(-x));
}

// fp16 mma, fp32 accumulate
__device__ __forceinline__ void mma_f16(float* c, const uint32_t* a, const uint32_t* b) {
    asm volatile(
        "mma.sync.aligned.m16n8k16.row.col.f32.f16.f16.f32 "
        "{%0,%1,%2,%3}, {%4,%5,%6,%7}, {%8,%9}, {%0,%1,%2,%3};\n"
        : "+f"(c[0]), "+f"(c[1]), "+f"(c[2]), "+f"(c[3])
        : "r"(a[0]), "r"(a[1]), "r"(a[2]), "r"(a[3]), "r"(b[0]), "r"(b[1]));
}

__device__ __forceinline__ void cpa16(void* dst, const void* src) {
    uint32_t d = (uint32_t)__cvta_generic_to_shared(dst);
    asm volatile("cp.async.cg.shared.global [%0], [%1], 16;" :: "r"(d), "l"(src));
}
#define CP_COMMIT asm volatile("cp.async.commit_group;" ::: "memory")
#define CP_WAIT0  asm volatile("cp.async.wait_group 0;" ::: "memory")

// ldmatrix x4
__device__ __forceinline__ void ldsm4(uint32_t* r, const __half* p) {
    uint32_t a = (uint32_t)__cvta_generic_to_shared(p);
    asm volatile("ldmatrix.sync.aligned.m8n8.x4.shared.b16 {%0,%1,%2,%3}, [%4];"
        : "=r"(r[0]), "=r"(r[1]), "=r"(r[2]), "=r"(r[3]) : "r"(a));
}
#define LDSMA(afr, base, SAx, rowbase, kg)                                        \
    ldsm4(afr, (base) + ((rowbase) + (lane & 15))*(SAx) + (kg) + ((lane >> 4) << 3))
#define LDSMB2(b4, bB, SBx, ncol, kk)                                             \
    ldsm4(b4, (bB) + ((ncol) + (lane & 7) + ((lane >> 4) << 3))*(SBx) + (kk) + (((lane >> 3) & 1) << 3))

// B buffer geometry: 128 n-rows x (32 k + 8 pad) halfs
#define SBh 40
#define BHB (128*SBh)

// ---------------- kernel 1: K/V projection + lattice gram ----------------
__global__ void prep_kernel(const float* __restrict__ cond,
                            const float* __restrict__ wk, const float* __restrict__ bk,
                            const float* __restrict__ wv, const float* __restrict__ bv,
                            const float* __restrict__ lat)
{
    int b = blockIdx.x;
    if (b < BB*TT) {
        __shared__ float s_c[DD];
        int d = threadIdx.x;
        s_c[d] = cond[b*DD + d];
        __syncthreads();
        float ka = bk[d], va = bv[d];
        #pragma unroll 8
        for (int k = 0; k < DD; k++) {
            float c = s_c[k];
            ka = fmaf(c, wk[k*DD + d], ka);
            va = fmaf(c, wv[k*DD + d], va);
        }
        g_KV16[b*DD + d] = __float2half(ka);
        g_KV16[KV_OFF + b*DD + d] = __float2half(va);
    } else {
        int bb = b - BB*TT;
        int t = threadIdx.x;
        if (t < 9) {
            int i = t / 3, k2 = t % 3;
            const float* L = lat + bb*9;
            g_lip[bb*9 + t] = L[i*3+0]*L[k2*3+0] + L[i*3+1]*L[k2*3+1] + L[i*3+2]*L[k2*3+2];
        }
    }
}

// ---------------- kernel 1b: convert+transpose weights ----------------
// cumulative: ew1T 36864 | ew2T 53248 | nw1T 86016 | nw2T 102400
//             wqT 118784 | woT 135168 | sw1T 139264 | sw2h 140288
__global__ void convw_kernel(const float* __restrict__ ew1, const float* __restrict__ ew2,
                             const float* __restrict__ nw1, const float* __restrict__ nw2,
                             const float* __restrict__ wq,  const float* __restrict__ wo,
                             const float* __restrict__ sw1, const float* __restrict__ sw2)
{
    int idx = blockIdx.x * 256 + threadIdx.x;
    if (idx < 36864) {
        int n = idx / 288, k = idx % 288;
        g_ew1T[idx] = (k < 268) ? __float2half(ew1[k*DD + n]) : __half(0.f);
    } else if (idx < 53248) {
        int j = idx - 36864; int n = j / DD, k = j % DD;
        g_ew2T[j] = __float2half(ew2[k*DD + n]);
    } else if (idx < 86016) {
        int j = idx - 53248; int n = j / 256, k = j % 256;
        g_nw1T[j] = __float2half(nw1[k*DD + n]);
    } else if (idx < 102400) {
        int j = idx - 86016; int n = j / DD, k = j % DD;
        g_nw2T[j] = __float2half(nw2[k*DD + n]);
    } else if (idx < 118784) {
        int j = idx - 102400; int n = j / DD, k = j % DD;
        g_wqT[j] = __float2half(wq[k*DD + n]);
    } else if (idx < 135168) {
        int j = idx - 118784; int n = j / DD, k = j % DD;
        g_woT[j] = __float2half(wo[k*DD + n]);
    } else if (idx < 139264) {
        int j = idx - 135168; int n = j / 32, k = j % 32;
        g_sw1T[j] = (k < 24) ? __float2half(sw1[k*DD + n]) : __half(0.f);
    } else if (idx < 140288) {
        int j = idx - 139264; int t = j >> 7, k = j & 127;
        g_sw2h[j] = __float2half(sw2[k*8 + t]);
    }
}

// ---------------- kernel 2: zero scatter buffers ----------------
__global__ void zero_kernel()
{
    int idx = blockIdx.x * blockDim.x + threadIdx.x;
    if (idx < NN*DD) g_agg[idx] = 0.f;
    if (idx < NN)    g_cnt[idx] = 0;
}

// ---------------- kernel 3: cross-attention, fp16 mma + fp16 KV ----------------
// Tile 64 nodes, 8 warps (2 wm x 4 wn), warp tile 32x32 (mf=2, nf=4).
#define AT 64
#define SQh 136    // h/q/ca/hid tile stride (halfs)
#define SBW2 136   // s_sw2h row stride (halfs)

__global__ __launch_bounds__(256, 2)
void attn_kernel(const float* __restrict__ nfeat, const float* __restrict__ frac,
                 const int* __restrict__ n2g,
                 const float* __restrict__ bq, const float* __restrict__ bo,
                 const float* __restrict__ sb1, const float* __restrict__ sb2)
{
    extern __shared__ char smraw[];
    __half* s_h    = (__half*)smraw;                // 64*136
    __half* s_hid  = s_h + AT*SQh;                  // 64*136
    __half* s_q    = s_hid + AT*SQh;                // 64*136
    __half* s_bsw  = s_q + AT*SQh;                  // 128*40
    __half* s_bb   = s_bsw + 128*SBh;               // 2*BHB
    __half* s_enc  = s_bb + 2*BHB;                  // 64*40
    __half* s_sw2h = s_enc + AT*40;                 // 8*136
    float*  s_sb1 = (float*)(s_sw2h + 8*SBW2);      // 128
    float*  s_sb2 = s_sb1 + 128;                    // 8
    float*  s_att = s_sb2 + 8;                      // 64*8
    __shared__ int s_g[AT];

    int tid = threadIdx.x, lane = tid & 31, wid = tid >> 5;
    int wm = wid >> 2, wn = wid & 3;
    int n0 = blockIdx.x * AT;
    int bn = tid >> 1, bseg = (tid & 1) * 16;

    if (tid < AT) s_g[tid] = n2g[min(n0 + tid, NN - 1)];

    // async: sw1T tile, sw2h, sb1, sb2, wqT chunk0
    cpa16(s_bsw + bn*SBh + bseg,     g_sw1T + bn*32 + bseg);
    cpa16(s_bsw + bn*SBh + bseg + 8, g_sw1T + bn*32 + bseg + 8);
    if (tid < 128) {
        int row = tid >> 4, seg = (tid & 15) * 8;
        cpa16(s_sw2h + row*SBW2 + seg, g_sw2h + row*DD + seg);
    }
    if (tid < 32) cpa16(s_sb1 + tid*4, sb1 + tid*4);
    if (tid < 2)  cpa16(s_sb2 + tid*4, sb2 + tid*4);
    cpa16(s_bb + bn*SBh + bseg,     g_wqT + bn*DD + bseg);
    cpa16(s_bb + bn*SBh + bseg + 8, g_wqT + bn*DD + bseg + 8);
    CP_COMMIT;

    // h tile: fp32 load + fp16 convert
    #pragma unroll
    for (int it = 0; it < 8; it++) {
        int idx = tid + it*256;
        int r = idx >> 5, c4 = (idx & 31) * 4;
        int n = min(n0 + r, NN - 1);
        float4 v = *(const float4*)(nfeat + (size_t)n*DD + c4);
        __half* dst = s_h + r*SQh + c4;
        *(__half2*)(dst)     = __floats2half2_rn(v.x, v.y);
        *(__half2*)(dst + 2) = __floats2half2_rn(v.z, v.w);
    }
    // enc
    {
        int n = tid >> 2, sub = tid & 3;
        int nn = min(n0 + n, NN - 1);
        float f0 = frac[nn*3+0], f1 = frac[nn*3+1], f2 = frac[nn*3+2];
        #pragma unroll
        for (int k = sub; k < 24; k += 4) {
            int ii = k % 12, c = ii >> 2, j = ii & 3;
            float fv = (c == 0) ? f0 : ((c == 1) ? f1 : f2);
            float ph = fv * ((float)(1 << j) * 3.14159265358979323846f);
            s_enc[n*40 + k] = __float2half((k < 12) ? sinf(ph) : cosf(ph));
        }
        s_enc[n*40 + 24 + sub] = __half(0.f);
        s_enc[n*40 + 28 + sub] = __half(0.f);
    }
    CP_WAIT0;
    __syncthreads();

    float acc[2][4][4];
    #pragma unroll
    for (int mf = 0; mf < 2; mf++)
        #pragma unroll
        for (int nf = 0; nf < 4; nf++)
            #pragma unroll
            for (int u = 0; u < 4; u++) acc[mf][nf][u] = 0.f;

    // ---- bias MLP layer1: hidden = silu(enc @ sw1 + sb1), one K=32 round ----
    #pragma unroll
    for (int kk = 0; kk < 32; kk += 16) {
        uint32_t afr[2][4];
        #pragma unroll
        for (int mf = 0; mf < 2; mf++) LDSMA(afr[mf], s_enc, 40, wm*32 + mf*16, kk);
        uint32_t bfr[4][2];
        LDSMB2(bfr[0], s_bsw, SBh, wn*32, kk);
        LDSMB2(bfr[2], s_bsw, SBh, wn*32 + 16, kk);
        #pragma unroll
        for (int mf = 0; mf < 2; mf++)
            #pragma unroll
            for (int nf = 0; nf < 4; nf++)
                mma_f16(acc[mf][nf], afr[mf], bfr[nf]);
    }
    #pragma unroll
    for (int mf = 0; mf < 2; mf++) {
        int r0 = wm*32 + mf*16 + (lane >> 2);
        #pragma unroll
        for (int nf = 0; nf < 4; nf++) {
            int n = wn*32 + nf*8 + (lane & 3)*2;
            float b0 = s_sb1[n], b1 = s_sb1[n + 1];
            *(__half2*)(s_hid + r0*SQh + n) =
                __floats2half2_rn(silu_f(acc[mf][nf][0] + b0), silu_f(acc[mf][nf][1] + b1));
            *(__half2*)(s_hid + (r0 + 8)*SQh + n) =
                __floats2half2_rn(silu_f(acc[mf][nf][2] + b0), silu_f(acc[mf][nf][3] + b1));
            #pragma unroll
            for (int u = 0; u < 4; u++) acc[mf][nf][u] = 0.f;
        }
    }

    // ---- GEMM Q = h @ wq: 4 rounds of K=32 ----
    for (int ct = 0; ct < 4; ct++) {
        __half* dbuf = s_bb + ((ct+1)&1)*BHB;
        const __half* src = (ct < 3) ? (g_wqT + (ct+1)*32) : g_woT;
        cpa16(dbuf + bn*SBh + bseg,     src + bn*DD + bseg);
        cpa16(dbuf + bn*SBh + bseg + 8, src + bn*DD + bseg + 8);
        CP_COMMIT;
        const __half* bB = s_bb + (ct & 1)*BHB;
        #pragma unroll
        for (int kk = 0; kk < 32; kk += 16) {
            int kg = ct*32 + kk;
            uint32_t afr[2][4];
            #pragma unroll
            for (int mf = 0; mf < 2; mf++) LDSMA(afr[mf], s_h, SQh, wm*32 + mf*16, kg);
            uint32_t bfr[4][2];
            LDSMB2(bfr[0], bB, SBh, wn*32, kk);
            LDSMB2(bfr[2], bB, SBh, wn*32 + 16, kk);
            #pragma unroll
            for (int mf = 0; mf < 2; mf++)
                #pragma unroll
                for (int nf = 0; nf < 4; nf++)
                    mma_f16(acc[mf][nf], afr[mf], bfr[nf]);
        }
        CP_WAIT0;
        __syncthreads();
    }
    #pragma unroll
    for (int mf = 0; mf < 2; mf++) {
        int r0 = wm*32 + mf*16 + (lane >> 2);
        #pragma unroll
        for (int nf = 0; nf < 4; nf++) {
            int n = wn*32 + nf*8 + (lane & 3)*2;
            float b0 = bq[n], b1 = bq[n + 1];
            *(__half2*)(s_q + r0*SQh + n) =
                __floats2half2_rn(acc[mf][nf][0] + b0, acc[mf][nf][1] + b1);
            *(__half2*)(s_q + (r0 + 8)*SQh + n) =
                __floats2half2_rn(acc[mf][nf][2] + b0, acc[mf][nf][3] + b1);
        }
    }
    __syncthreads();

    // ---- bias MLP layer2 via MMA: bias[64,8] = hidden @ sw2 (warps 0-3) ----
    if (wid < 4) {
        float bacc[4] = {0.f, 0.f, 0.f, 0.f};
        #pragma unroll
        for (int kk = 0; kk < 128; kk += 16) {
            uint32_t afr[4];
            LDSMA(afr, s_hid, SQh, wid*16, kk);
            const __half* bp = s_sw2h + (lane >> 2)*SBW2 + kk + (lane & 3)*2;
            uint32_t bfr[2];
            bfr[0] = *(const uint32_t*)(bp);
            bfr[1] = *(const uint32_t*)(bp + 8);
            mma_f16(bacc, afr, bfr);
        }
        int r0 = wid*16 + (lane >> 2);
        int t = (lane & 3)*2;
        s_att[r0*8 + t]         = bacc[0];
        s_att[r0*8 + t + 1]     = bacc[1];
        s_att[(r0 + 8)*8 + t]     = bacc[2];
        s_att[(r0 + 8)*8 + t + 1] = bacc[3];
    }
    __syncthreads();

    // ---- scores (fp16 K) + bias + softmax: thread = (node, sub of 4) ----
    {
        int n = tid >> 2, sub = tid & 3;
        int gg = s_g[n];
        int t0 = sub*2, t1 = t0 + 1;
        const __half2* K0 = (const __half2*)(g_KV16 + (size_t)(gg*TT + t0)*DD);
        const __half2* K1 = (const __half2*)(g_KV16 + (size_t)(gg*TT + t1)*DD);
        const __half2* qq = (const __half2*)(s_q + n*SQh);
        float sc0 = 0.f, sc1 = 0.f;
        #pragma unroll 8
        for (int k2 = 0; k2 < 64; k2++) {
            float2 q = __half22float2(qq[k2]);
            float2 a = __half22float2(K0[k2]);
            float2 b = __half22float2(K1[k2]);
            sc0 = fmaf(q.x, a.x, sc0); sc0 = fmaf(q.y, a.y, sc0);
            sc1 = fmaf(q.x, b.x, sc1); sc1 = fmaf(q.y, b.y, sc1);
        }
        float v0 = sc0 * 0.08838834764831845f + s_att[n*8 + t0] + s_sb2[t0];
        float v1 = sc1 * 0.08838834764831845f + s_att[n*8 + t1] + s_sb2[t1];
        float m = fmaxf(v0, v1);
        m = fmaxf(m, __shfl_xor_sync(0xffffffffu, m, 1, 4));
        m = fmaxf(m, __shfl_xor_sync(0xffffffffu, m, 2, 4));
        float e0 = __expf(v0 - m), e1 = __expf(v1 - m);
        float s = e0 + e1;
        s += __shfl_xor_sync(0xffffffffu, s, 1, 4);
        s += __shfl_xor_sync(0xffffffffu, s, 2, 4);
        float inv = __fdividef(1.f, s);
        s_att[n*8 + t0] = e0 * inv;
        s_att[n*8 + t1] = e1 * inv;
    }
    __syncthreads();

    // ---- ca = attn @ V (fp16 V) -> s_q ----
    #pragma unroll
    for (int it = 0; it < 16; it++) {
        int idx = tid + it*256;
        int n = idx >> 6, c = (idx & 63) * 2;
        const __half* Vr = g_KV16 + KV_OFF + (size_t)s_g[n]*TT*DD + c;
        const float* at = s_att + n*8;
        float a0 = 0.f, a1 = 0.f;
        #pragma unroll
        for (int t = 0; t < 8; t++) {
            float2 v = __half22float2(*(const __half2*)(Vr + t*DD));
            a0 = fmaf(at[t], v.x, a0);
            a1 = fmaf(at[t], v.y, a1);
        }
        *(__half2*)(s_q + n*SQh + c) = __floats2half2_rn(a0, a1);
    }
    __syncthreads();

    float acc2[2][4][4];
    #pragma unroll
    for (int mf = 0; mf < 2; mf++)
        #pragma unroll
        for (int nf = 0; nf < 4; nf++)
            #pragma unroll
            for (int u = 0; u < 4; u++) acc2[mf][nf][u] = 0.f;

    // ---- GEMM out = ca @ wo: 4 rounds (chunk0 already in buf0) ----
    for (int c = 0; c < 4; c++) {
        if (c < 3) {
            __half* dbuf = s_bb + ((c+1)&1)*BHB;
            const __half* src = g_woT + (c+1)*32;
            cpa16(dbuf + bn*SBh + bseg,     src + bn*DD + bseg);
            cpa16(dbuf + bn*SBh + bseg + 8, src + bn*DD + bseg + 8);
            CP_COMMIT;
        }
        const __half* bB = s_bb + (c & 1)*BHB;
        #pragma unroll
        for (int kk = 0; kk < 32; kk += 16) {
            int kg = c*32 + kk;
            uint32_t afr[2][4];
            #pragma unroll
            for (int mf = 0; mf < 2; mf++) LDSMA(afr[mf], s_q, SQh, wm*32 + mf*16, kg);
            uint32_t bfr[4][2];
            LDSMB2(bfr[0], bB, SBh, wn*32, kk);
            LDSMB2(bfr[2], bB, SBh, wn*32 + 16, kk);
            #pragma unroll
            for (int mf = 0; mf < 2; mf++)
                #pragma unroll
                for (int nf = 0; nf < 4; nf++)
                    mma_f16(acc2[mf][nf], afr[mf], bfr[nf]);
        }
        if (c < 3) { CP_WAIT0; }
        __syncthreads();
    }

    // epilogue: g_h16 = half(h + ca@wo + bo)
    #pragma unroll
    for (int mf = 0; mf < 2; mf++) {
        #pragma unroll
        for (int rr = 0; rr < 2; rr++) {
            int m = wm*32 + mf*16 + (lane >> 2) + rr*8;
            int n = n0 + m;
            if (n < NN) {
                __half* orow = g_h16 + (size_t)n*DD;
                const __half* hrow = s_h + m*SQh;
                #pragma unroll
                for (int nf = 0; nf < 4; nf++) {
                    int col = wn*32 + nf*8 + (lane & 3)*2;
                    float v0 = __half2float(hrow[col])     + acc2[mf][nf][rr*2 + 0] + bo[col];
                    float v1 = __half2float(hrow[col + 1]) + acc2[mf][nf][rr*2 + 1] + bo[col + 1];
                    *(__half2*)(orow + col) = __floats2half2_rn(v0, v1);
                }
            }
        }
    }
}

// ---------------- kernel 4: edge MLP, fp16 + ldmatrix ----------------
#define TM 128
#define SAh 296

__global__ __launch_bounds__(256, 2)
void edge_kernel(const float* __restrict__ frac,
                 const int* __restrict__ edges, const int* __restrict__ e2g,
                 const float* __restrict__ eb1, const float* __restrict__ eb2)
{
    extern __shared__ __half smh[];
    __half* s_a  = smh;               // TM*SAh
    __half* s_bb = smh + TM*SAh;      // 2*BHB
    __shared__ int s_i[TM], s_j[TM];

    int tid  = threadIdx.x, lane = tid & 31, wid = tid >> 5;
    int wm = wid >> 2, wn = wid & 3;
    int e0 = blockIdx.x * TM;
    int bn = tid >> 1, bseg = (tid & 1) * 16;

    if (tid < TM) {
        s_i[tid] = edges[e0 + tid];
        s_j[tid] = edges[EE + e0 + tid];
    }
    __syncthreads();

    #pragma unroll
    for (int it = 0; it < 16; it++) {
        int idx = tid + it*256;
        int r = idx >> 4, seg = idx & 15;
        int e = r >> 1, p = r & 1;
        int node = p ? s_j[e] : s_i[e];
        cpa16(s_a + e*SAh + p*DD + seg*8, g_h16 + (size_t)node*DD + seg*8);
    }
    cpa16(s_bb + bn*SBh + bseg,     g_ew1T + bn*288 + bseg);
    cpa16(s_bb + bn*SBh + bseg + 8, g_ew1T + bn*288 + bseg + 8);
    CP_COMMIT;

    if (tid < TM) {
        int e = tid;
        const float* lp = g_lip + e2g[e0 + e]*9;
        #pragma unroll
        for (int u = 0; u < 9; u++) s_a[e*SAh + 256 + u] = __float2half(lp[u]);
        int ii = s_i[e], jj = s_j[e];
        #pragma unroll
        for (int c = 0; c < 3; c++) {
            float dd = frac[jj*3 + c] - frac[ii*3 + c];
            dd -= floorf(dd);
            s_a[e*SAh + 265 + c] = __float2half(dd);
        }
        #pragma unroll
        for (int u = 268; u < 288; u++) s_a[e*SAh + u] = __half(0.f);
        atomicAdd(&g_cnt[ii], 1);
    }

    float acc[4][4][4];
    #pragma unroll
    for (int mf = 0; mf < 4; mf++)
        #pragma unroll
        for (int nf = 0; nf < 4; nf++)
            #pragma unroll
            for (int u = 0; u < 4; u++) acc[mf][nf][u] = 0.f;

    CP_WAIT0;
    __syncthreads();

    // ---- GEMM1: K=288, 9 rounds of K=32 ----
    for (int ct = 0; ct < 9; ct++) {
        __half* dbuf = s_bb + ((ct+1)&1)*BHB;
        const __half* src; int rstr;
        if (ct < 8) { src = g_ew1T + (ct+1)*32; rstr = 288; }
        else        { src = g_ew2T;             rstr = 128; }
        cpa16(dbuf + bn*SBh + bseg,     src + (size_t)bn*rstr + bseg);
        cpa16(dbuf + bn*SBh + bseg + 8, src + (size_t)bn*rstr + bseg + 8);
        CP_COMMIT;
        const __half* bB = s_bb + (ct & 1)*BHB;
        #pragma unroll
        for (int kk = 0; kk < 32; kk += 16) {
            int kg = ct*32 + kk;
            uint32_t afr[4][4];
            #pragma unroll
            for (int mf = 0; mf < 4; mf++) LDSMA(afr[mf], s_a, SAh, wm*64 + mf*16, kg);
            uint32_t bfr[4][2];
            LDSMB2(bfr[0], bB, SBh, wn*32, kk);
            LDSMB2(bfr[2], bB, SBh, wn*32 + 16, kk);
            #pragma unroll
            for (int mf = 0; mf < 4; mf++)
                #pragma unroll
                for (int nf = 0; nf < 4; nf++)
                    mma_f16(acc[mf][nf], afr[mf], bfr[nf]);
        }
        CP_WAIT0;
        __syncthreads();
    }

    // hidden = silu(acc + eb1) -> s_a cols 0..127
    #pragma unroll
    for (int mf = 0; mf < 4; mf++) {
        int r0 = wm*64 + mf*16 + (lane >> 2);
        #pragma unroll
        for (int nf = 0; nf < 4; nf++) {
            int n = wn*32 + nf*8 + (lane & 3)*2;
            float b0 = eb1[n], b1 = eb1[n + 1];
            *(__half2*)(s_a + r0*SAh + n) =
                __floats2half2_rn(silu_f(acc[mf][nf][0] + b0), silu_f(acc[mf][nf][1] + b1));
            *(__half2*)(s_a + (r0 + 8)*SAh + n) =
                __floats2half2_rn(silu_f(acc[mf][nf][2] + b0), silu_f(acc[mf][nf][3] + b1));
            #pragma unroll
            for (int u = 0; u < 4; u++) acc[mf][nf][u] = 0.f;
        }
    }
    __syncthreads();

    // ---- GEMM2: K=128, 4 rounds; chunk c in buf[(1+c)&1] ----
    for (int c = 0; c < 4; c++) {
        if (c < 3) {
            __half* dbuf = s_bb + (c & 1)*BHB;
            const __half* src = g_ew2T + (c+1)*32;
            cpa16(dbuf + bn*SBh + bseg,     src + bn*DD + bseg);
            cpa16(dbuf + bn*SBh + bseg + 8, src + bn*DD + bseg + 8);
            CP_COMMIT;
        }
        const __half* bB = s_bb + ((1 + c) & 1)*BHB;
        #pragma unroll
        for (int kk = 0; kk < 32; kk += 16) {
            int kg = c*32 + kk;
            uint32_t afr[4][4];
            #pragma unroll
            for (int mf = 0; mf < 4; mf++) LDSMA(afr[mf], s_a, SAh, wm*64 + mf*16, kg);
            uint32_t bfr[4][2];
            LDSMB2(bfr[0], bB, SBh, wn*32, kk);
            LDSMB2(bfr[2], bB, SBh, wn*32 + 16, kk);
            #pragma unroll
            for (int mf = 0; mf < 4; mf++)
                #pragma unroll
                for (int nf = 0; nf < 4; nf++)
                    mma_f16(acc[mf][nf], afr[mf], bfr[nf]);
        }
        if (c < 3) { CP_WAIT0; }
        __syncthreads();
    }

    // epilogue: silu + bias, red.v2 scatter into g_agg (fp32)
    #pragma unroll
    for (int mf = 0; mf < 4; mf++) {
        #pragma unroll
        for (int rr = 0; rr < 2; rr++) {
            int m = wm*64 + mf*16 + (lane >> 2) + rr*8;
            float* ap = g_agg + (size_t)s_i[m]*DD;
            #pragma unroll
            for (int nf = 0; nf < 4; nf++) {
                int n = wn*32 + nf*8 + (lane & 3)*2;
                float v0 = silu_f(acc[mf][nf][rr*2 + 0] + eb2[n]);
                float v1 = silu_f(acc[mf][nf][rr*2 + 1] + eb2[n + 1]);
                asm volatile("red.global.add.v2.f32 [%0], {%1, %2};"
                             :: "l"(ap + n), "f"(v0), "f"(v1) : "memory");
            }
        }
    }
}

// ---------------- kernel 5: node MLP, fp16 + ldmatrix ----------------
#define TN 128
#define SAn 264

__global__ __launch_bounds__(256, 2)
void node_kernel(const float* __restrict__ nfeat,
                 const float* __restrict__ nb1, const float* __restrict__ nb2,
                 float* __restrict__ out)
{
    extern __shared__ __half smh[];
    __half* s_a  = smh;               // TN*SAn
    __half* s_bb = smh + TN*SAn;      // 2*BHB
    __shared__ float s_cnt[TN];

    int tid  = threadIdx.x, lane = tid & 31, wid = tid >> 5;
    int wm = wid >> 2, wn = wid & 3;
    int n0 = blockIdx.x * TN;
    int bn = tid >> 1, bseg = (tid & 1) * 16;

    if (tid < TN) {
        int n = min(n0 + tid, NN - 1);
        s_cnt[tid] = fmaxf((float)g_cnt[n], 1.f);
    }
    #pragma unroll
    for (int it = 0; it < 8; it++) {
        int idx = tid + it*256;
        int r = idx >> 4, seg = idx & 15;
        int n = min(n0 + r, NN - 1);
        cpa16(s_a + r*SAn + seg*8, g_h16 + (size_t)n*DD + seg*8);
    }
    cpa16(s_bb + bn*SBh + bseg,     g_nw1T + bn*256 + bseg);
    cpa16(s_bb + bn*SBh + bseg + 8, g_nw1T + bn*256 + bseg + 8);
    CP_COMMIT;
    __syncthreads();

    #pragma unroll
    for (int it = 0; it < 16; it++) {
        int idx = tid + it*256;
        int r = idx >> 5, c4 = (idx & 31) * 4;
        int n = min(n0 + r, NN - 1);
        float inv = __fdividef(1.f, s_cnt[r]);
        float4 v = *(const float4*)(g_agg + (size_t)n*DD + c4);
        __half* dst = s_a + r*SAn + DD + c4;
        *(__half2*)(dst)     = __floats2half2_rn(v.x * inv, v.y * inv);
        *(__half2*)(dst + 2) = __floats2half2_rn(v.z * inv, v.w * inv);
    }

    float acc[4][4][4];
    #pragma unroll
    for (int mf = 0; mf < 4; mf++)
        #pragma unroll
        for (int nf = 0; nf < 4; nf++)
            #pragma unroll
            for (int u = 0; u < 4; u++) acc[mf][nf][u] = 0.f;

    CP_WAIT0;
    __syncthreads();

    // ---- GEMM1: K=256, 8 rounds of K=32 ----
    for (int ct = 0; ct < 8; ct++) {
        __half* dbuf = s_bb + ((ct+1)&1)*BHB;
        const __half* src; int rstr;
        if (ct < 7) { src = g_nw1T + (ct+1)*32; rstr = 256; }
        else        { src = g_nw2T;             rstr = 128; }
        cpa16(dbuf + bn*SBh + bseg,     src + (size_t)bn*rstr + bseg);
        cpa16(dbuf + bn*SBh + bseg + 8, src + (size_t)bn*rstr + bseg + 8);
        CP_COMMIT;
        const __half* bB = s_bb + (ct & 1)*BHB;
        #pragma unroll
        for (int kk = 0; kk < 32; kk += 16) {
            int kg = ct*32 + kk;
            uint32_t afr[4][4];
            #pragma unroll
            for (int mf = 0; mf < 4; mf++) LDSMA(afr[mf], s_a, SAn, wm*64 + mf*16, kg);
            uint32_t bfr[4][2];
            LDSMB2(bfr[0], bB, SBh, wn*32, kk);
            LDSMB2(bfr[2], bB, SBh, wn*32 + 16, kk);
            #pragma unroll
            for (int mf = 0; mf < 4; mf++)
                #pragma unroll
                for (int nf = 0; nf < 4; nf++)
                    mma_f16(acc[mf][nf], afr[mf], bfr[nf]);
        }
        CP_WAIT0;
        __syncthreads();
    }

    // hidden -> s_a cols 0..127
    #pragma unroll
    for (int mf = 0; mf < 4; mf++) {
        int r0 = wm*64 + mf*16 + (lane >> 2);
        #pragma unroll
        for (int nf = 0; nf < 4; nf++) {
            int n = wn*32 + nf*8 + (lane & 3)*2;
            float b0 = nb1[n], b1 = nb1[n + 1];
            *(__half2*)(s_a + r0*SAn + n) =
                __floats2half2_rn(silu_f(acc[mf][nf][0] + b0), silu_f(acc[mf][nf][1] + b1));
            *(__half2*)(s_a + (r0 + 8)*SAn + n) =
                __floats2half2_rn(silu_f(acc[mf][nf][2] + b0), silu_f(acc[mf][nf][3] + b1));
            #pragma unroll
            for (int u = 0; u < 4; u++) acc[mf][nf][u] = 0.f;
        }
    }
    __syncthreads();

    // ---- GEMM2: K=128, 4 rounds; chunk c in buf[c&1] ----
    for (int c = 0; c < 4; c++) {
        if (c < 3) {
            __half* dbuf = s_bb + ((c+1)&1)*BHB;
            const __half* src = g_nw2T + (c+1)*32;
            cpa16(dbuf + bn*SBh + bseg,     src + bn*DD + bseg);
            cpa16(dbuf + bn*SBh + bseg + 8, src + bn*DD + bseg + 8);
            CP_COMMIT;
        }
        const __half* bB = s_bb + (c & 1)*BHB;
        #pragma unroll
        for (int kk = 0; kk < 32; kk += 16) {
            int kg = c*32 + kk;
            uint32_t afr[4][4];
            #pragma unroll
            for (int mf = 0; mf < 4; mf++) LDSMA(afr[mf], s_a, SAn, wm*64 + mf*16, kg);
            uint32_t bfr[4][2];
            LDSMB2(bfr[0], bB, SBh, wn*32, kk);
            LDSMB2(bfr[2], bB, SBh, wn*32 + 16, kk);
            #pragma unroll
            for (int mf = 0; mf < 4; mf++)
                #pragma unroll
                for (int nf = 0; nf < 4; nf++)
                    mma_f16(acc[mf][nf], afr[mf], bfr[nf]);
        }
        if (c < 3) { CP_WAIT0; }
        __syncthreads();
    }

    // epilogue: out = nfeat + silu(acc + nb2)
    #pragma unroll
    for (int mf = 0; mf < 4; mf++) {
        #pragma unroll
        for (int rr = 0; rr < 2; rr++) {
            int m = wm*64 + mf*16 + (lane >> 2) + rr*8;
            int n = n0 + m;
            if (n < NN) {
                const float* nfr = nfeat + (size_t)n*DD;
                float* orow = out + (size_t)n*DD;
                #pragma unroll
                for (int nf = 0; nf < 4; nf++) {
                    int col = wn*32 + nf*8 + (lane & 3)*2;
                    orow[col]     = nfr[col]     + silu_f(acc[mf][nf][rr*2 + 0] + nb2[col]);
                    orow[col + 1] = nfr[col + 1] + silu_f(acc[mf][nf][rr*2 + 1] + nb2[col + 1]);
                }
            }
        }
    }
}

// ---------------- launch ----------------
extern "C" void kernel_launch(void* const* d_in, const int* in_sizes, int n_in,
                              void* d_out, int out_size)
{
    const float* node_features = (const float*)d_in[0];
    const float* cond = (const float*)d_in[1];
    const int*   n2g  = (const int*)d_in[2];
    const float* frac = (const float*)d_in[3];
    const float* lat  = (const float*)d_in[4];
    const int*   edges= (const int*)d_in[5];
    const int*   e2g  = (const int*)d_in[6];
    const float* wq = (const float*)d_in[7];
    const float* bq = (const float*)d_in[8];
    const float* wk = (const float*)d_in[9];
    const float* bk = (const float*)d_in[10];
    const float* wv = (const float*)d_in[11];
    const float* bv = (const float*)d_in[12];
    const float* wo = (const float*)d_in[13];
    const float* bo = (const float*)d_in[14];
    const float* sw1= (const float*)d_in[15];
    const float* sb1= (const float*)d_in[16];
    const float* sw2= (const float*)d_in[17];
    const float* sb2= (const float*)d_in[18];
    const float* ew1= (const float*)d_in[19];
    const float* eb1= (const float*)d_in[20];
    const float* ew2= (const float*)d_in[21];
    const float* eb2= (const float*)d_in[22];
    const float* nw1= (const float*)d_in[23];
    const float* nb1= (const float*)d_in[24];
    const float* nw2= (const float*)d_in[25];
    const float* nb2= (const float*)d_in[26];
    float* out = (float*)d_out;

    const int attn_smem = (3*AT*SQh + 128*SBh + 2*BHB + AT*40 + 8*SBW2) * 2
                        + (128 + 8 + AT*8) * 4;                      // ~92.9 KB
    const int edge_smem = (TM*SAh + 2*BHB) * 2;                      // 96,256 B
    const int node_smem = (TN*SAn + 2*BHB) * 2;                      // 88,064 B
    cudaFuncSetAttribute(attn_kernel, cudaFuncAttributeMaxDynamicSharedMemorySize, attn_smem);
    cudaFuncSetAttribute(edge_kernel, cudaFuncAttributeMaxDynamicSharedMemorySize, edge_smem);
    cudaFuncSetAttribute(node_kernel, cudaFuncAttributeMaxDynamicSharedMemorySize, node_smem);

    prep_kernel<<<BB*TT + BB, 128>>>(cond, wk, bk, wv, bv, lat);
    convw_kernel<<<549, 256>>>(ew1, ew2, nw1, nw2, wq, wo, sw1, sw2);
    zero_kernel<<<(NN*DD + 255) / 256, 256>>>();
    attn_kernel<<<(NN + AT - 1) / AT, 256, attn_smem>>>(node_features, frac, n2g,
                                                        bq, bo, sb1, sb2);
    edge_kernel<<<EE / TM, 256, edge_smem>>>(frac, edges, e2g, eb1, eb2);
    node_kernel<<<(NN + TN - 1) / TN, 256, node_smem>>>(node_features, nb1, nb2, out);
}